// round 9
// baseline (speedup 1.0000x reference)
#include <cuda_runtime.h>
#include <cuda_bf16.h>
#include <math.h>
#include <stdint.h>

#define NN     8000
#define NE     64000
#define BATCH  64
#define NG     12
#define HID    128
#define LAY    3
#define IN_S   16
#define OUT_S  8
#define WHID   512
#define ETILES 6000   // 768000/128
#define NTILES 750    // 96000/128

// smem matrix: 128 rows x 136 bf16 (272B stride, conflict-free ldmatrix)
#define MSTRIDE   136
#define MBYTES    (128*MSTRIDE*2)   // 34816
#define OFF_AH    0
#define OFF_AL    34816
#define OFF_BH    69632
#define OFF_BL    104448
#define OFF_UH    139264
#define OFF_UL    174080
#define SM_EDGE   139264
#define SM_MLP    208896
#define TSTRIDE   132               // f32 epilogue tile stride

// ---------------- helpers ----------------
__device__ __forceinline__ uint32_t smem_u32(const void* p) {
    uint32_t a;
    asm("{ .reg .u64 t; cvta.to.shared.u64 t, %1; cvt.u32.u64 %0, t; }" : "=r"(a) : "l"(p));
    return a;
}
__device__ __forceinline__ void ldsm4(uint32_t addr, uint32_t* r) {
    asm volatile("ldmatrix.sync.aligned.m8n8.x4.shared.b16 {%0,%1,%2,%3}, [%4];"
        : "=r"(r[0]), "=r"(r[1]), "=r"(r[2]), "=r"(r[3]) : "r"(addr));
}
__device__ __forceinline__ void mma16816(float* d, const uint32_t* a, uint32_t b0, uint32_t b1) {
    asm volatile("mma.sync.aligned.m16n8k16.row.col.f32.bf16.bf16.f32 "
        "{%0,%1,%2,%3}, {%4,%5,%6,%7}, {%8,%9}, {%0,%1,%2,%3};"
        : "+f"(d[0]), "+f"(d[1]), "+f"(d[2]), "+f"(d[3])
        : "r"(a[0]), "r"(a[1]), "r"(a[2]), "r"(a[3]), "r"(b0), "r"(b1));
}
__device__ __forceinline__ uint32_t pack2(float a, float b) {
    __nv_bfloat162 h; h.x = __float2bfloat16(a); h.y = __float2bfloat16(b);
    return *reinterpret_cast<uint32_t*>(&h);
}
__device__ __forceinline__ uint32_t pack2lo(float a, float b, uint32_t hi) {
    __nv_bfloat162 h = *reinterpret_cast<__nv_bfloat162*>(&hi);
    __nv_bfloat162 l; l.x = __float2bfloat16(a - __bfloat162float(h.x));
    l.y = __float2bfloat16(b - __bfloat162float(h.y));
    return *reinterpret_cast<uint32_t*>(&l);
}
__device__ __forceinline__ float gelu(float x) {
    return x * 0.5f * (1.0f + erff(x * 0.70710678118654752f));
}

// C[128x128] += A[128x128] @ B[n][k]^T with bf16x3 split. acc[64]: [ntile0..15][4]
__device__ __forceinline__ void gemm128(uint32_t sb, uint32_t aH, uint32_t aL,
                                        uint32_t bH, uint32_t bL,
                                        float* acc, int wid, int lane) {
    uint32_t arow  = wid*16 + (lane & 15);
    uint32_t acolo = (lane >> 4) << 3;
    uint32_t brow  = ((lane >> 4) << 3) + (lane & 7);
    uint32_t bcolo = ((lane >> 3) & 1) << 3;
    #pragma unroll
    for (int kt = 0; kt < 8; kt++) {
        uint32_t k0 = kt * 16;
        uint32_t aoff = (arow*MSTRIDE + k0 + acolo) * 2;
        uint32_t ah[4], al[4];
        ldsm4(sb + aH + aoff, ah);
        ldsm4(sb + aL + aoff, al);
        #pragma unroll
        for (int g = 0; g < 8; g++) {
            uint32_t boff = ((g*16 + brow)*MSTRIDE + k0 + bcolo) * 2;
            uint32_t bh[4], bl[4];
            ldsm4(sb + bH + boff, bh);
            ldsm4(sb + bL + boff, bl);
            float* a0 = acc + g*8;
            mma16816(a0,     ah, bh[0], bh[1]);
            mma16816(a0,     ah, bl[0], bl[1]);
            mma16816(a0,     al, bh[0], bh[1]);
            mma16816(a0 + 4, ah, bh[2], bh[3]);
            mma16816(a0 + 4, ah, bl[2], bl[3]);
            mma16816(a0 + 4, al, bh[2], bh[3]);
        }
    }
}
// copy unpadded 128x128 bf16 gmem blob -> padded smem matrix
__device__ __forceinline__ void cp_blob(char* dst, const __nv_bfloat16* src, int tid) {
    const uint4* s = (const uint4*)src;
    for (int i = tid; i < 2048; i += 256) {
        int row = i >> 4, j = i & 15;
        ((uint4*)dst)[row*17 + j] = s[i];
    }
}

// ---------------- device scratch ----------------
__device__ float g_grid0[NG*3];
__device__ float g_kbsh[NG*NG*HID];
__device__ float g_fk[LAY*NG*NG*HID];
__device__ float g_nodegrid[NN*NG*3];
__device__ float g_h[NN*NG*HID];
__device__ float g_agg[NN*NG*HID];
__device__ float g_readout[NN*NG*9];
__device__ __nv_bfloat16 g_kbspH[(size_t)ETILES*16384];
__device__ __nv_bfloat16 g_kbspL[(size_t)ETILES*16384];
__device__ __nv_bfloat16 g_hnH[(size_t)NTILES*16384];
__device__ __nv_bfloat16 g_hnL[(size_t)NTILES*16384];
__device__ __nv_bfloat16 g_Bsp2H[16384],   g_Bsp2L[16384];
__device__ __nv_bfloat16 g_BWkH[3*16384],  g_BWkL[3*16384];
__device__ __nv_bfloat16 g_BW1H[12*16384], g_BW1L[12*16384];
__device__ __nv_bfloat16 g_BW2H[12*16384], g_BW2L[12*16384];

extern __shared__ __align__(16) char dsm[];

// ---------------- setup ----------------
__global__ void k_init_grid0() {
    int i = threadIdx.x;
    if (i < NG) {
        float fi = (float)i;
        float theta = (6.2831853071795865f * fi) / 1.6180339887498949f;
        float z = 1.0f - (2.0f*fi + 1.0f) / (float)NG;
        float r = sqrtf(fmaxf(1.0f - z*z, 0.0f));
        g_grid0[i*3+0] = r*cosf(theta); g_grid0[i*3+1] = r*sinf(theta); g_grid0[i*3+2] = z;
    }
}

// W[K x N] f32 -> transposed blobs Wt[n][k] bf16 hi/lo; blob = (n>>7)*(K>>7)+(k>>7)
__global__ void k_packw(const float* __restrict__ src, __nv_bfloat16* dh,
                        __nv_bfloat16* dl, int K, int N) {
    int idx = blockIdx.x * blockDim.x + threadIdx.x;
    if (idx >= K*N) return;
    int k = idx / N, n = idx % N;
    int blob = (n >> 7) * (K >> 7) + (k >> 7);
    int off = (n & 127)*128 + (k & 127);
    float v = src[idx];
    __nv_bfloat16 h = __float2bfloat16(v);
    dh[(size_t)blob*16384 + off] = h;
    dl[(size_t)blob*16384 + off] = __float2bfloat16(v - __bfloat162float(h));
}

__global__ void k_kbsh(const float* __restrict__ Wsh1, const float* __restrict__ bsh1,
                       const float* __restrict__ Wsh2, const float* __restrict__ bsh2) {
    int row = blockIdx.x, p = row/NG, o = row%NG, c = threadIdx.x;
    __shared__ float h1[HID];
    float t = g_grid0[p*3]*g_grid0[o*3] + g_grid0[p*3+1]*g_grid0[o*3+1] + g_grid0[p*3+2]*g_grid0[o*3+2];
    h1[c] = gelu(bsh1[c] + t*Wsh1[c] + t*t*Wsh1[HID+c] + t*t*t*Wsh1[2*HID+c]);
    __syncthreads();
    float acc = bsh2[c];
    #pragma unroll 8
    for (int k = 0; k < HID; k++) acc += h1[k]*Wsh2[k*HID+c];
    g_kbsh[row*HID + c] = gelu(acc);
}

__global__ void k_fk(const float* __restrict__ Wfk) {
    int blk = blockIdx.x, l = blk/(NG*NG), row = blk%(NG*NG), c = threadIdx.x;
    __shared__ float kb[HID];
    kb[c] = g_kbsh[row*HID + c];
    __syncthreads();
    const float* W = Wfk + (size_t)l*HID*HID;
    float acc = 0.f;
    #pragma unroll 8
    for (int b = 0; b < HID; b++) acc += kb[b]*W[b*HID+c];
    g_fk[((size_t)l*NG*NG + row)*HID + c] = acc;
}

__global__ void k_nodeinit(const float* __restrict__ x, const float* __restrict__ vec,
                           const float* __restrict__ Q, const int* __restrict__ batch,
                           const float* __restrict__ Wemb) {
    int i = blockIdx.x, t = threadIdx.x;
    __shared__ float ng[NG][3], xv[NG][2], xs[IN_S];
    int b = batch[i];
    if (t < 36) {
        int n = t/3, d = t%3; float s = 0.f;
        #pragma unroll
        for (int j = 0; j < 3; j++) s += Q[b*9 + d*3 + j]*g_grid0[n*3+j];
        ng[n][d] = s; g_nodegrid[i*36 + t] = s;
    }
    if (t >= 64 && t < 64+IN_S) xs[t-64] = x[i*IN_S + (t-64)];
    if (t < 108) g_readout[(size_t)i*108 + t] = 0.f;
    __syncthreads();
    if (t < 24) {
        int n = t/2, v = t%2;
        xv[n][v] = vec[i*6+v*3]*ng[n][0] + vec[i*6+v*3+1]*ng[n][1] + vec[i*6+v*3+2]*ng[n][2];
    }
    __syncthreads();
    int c = t; float hx = 0.f;
    #pragma unroll
    for (int s = 0; s < IN_S; s++) hx += xs[s]*Wemb[s*HID+c];
    float w16 = Wemb[16*HID+c], w17 = Wemb[17*HID+c];
    #pragma unroll
    for (int n = 0; n < NG; n++)
        g_h[(size_t)i*NG*HID + n*HID + c] = hx + xv[n][0]*w16 + xv[n][1]*w17;
}

// ---------------- K4: kbsp tile (SIMT front + mma MLP2) ----------------
__global__ void __launch_bounds__(256) k_kbsp(
        const float* __restrict__ pos, const int* __restrict__ ei,
        const float* __restrict__ Wsp1, const float* __restrict__ bsp1,
        const float* __restrict__ bsp2) {
    __shared__ float sW1[14*HID], sb1[HID], sb2[HID];
    int t = blockIdx.x, tid = threadIdx.x;
    int wid = tid >> 5, lane = tid & 31;
    for (int i = tid; i < 14*HID; i += 256) sW1[i] = Wsp1[i];
    if (tid < HID) { sb1[tid] = bsp1[tid]; sb2[tid] = bsp2[tid]; }
    uint32_t sb = smem_u32(dsm);
    // ---- front: h1 -> A blobs (hi/lo) ----
    int r = tid >> 1, half = tid & 1;
    int gr = t*128 + r, e = gr/12, p = gr - e*12;
    int sn = ei[e], rn = ei[NE + e];
    float rx = pos[sn*3]-pos[rn*3], ry = pos[sn*3+1]-pos[rn*3+1], rz = pos[sn*3+2]-pos[rn*3+2];
    float gx = g_nodegrid[rn*36+p*3], gy = g_nodegrid[rn*36+p*3+1], gz = g_nodegrid[rn*36+p*3+2];
    float a = rx*gx + ry*gy + rz*gz;
    float vx = rx-a*gx, vy = ry-a*gy, vz = rz-a*gz;
    float bb = sqrtf(vx*vx + vy*vy + vz*vz);
    float pf[14] = {a, bb, a*a, a*bb, bb*a, bb*bb, a*a*a, a*a*bb, a*bb*a, a*bb*bb,
                    bb*a*a, bb*a*bb, bb*bb*a, bb*bb*bb};
    __syncthreads();   // sW1/sb1 ready
    for (int c2 = half*32; c2 < half*32 + 32; c2++) {
        float f0 = sb1[2*c2], f1 = sb1[2*c2+1];
        #pragma unroll
        for (int j = 0; j < 14; j++) {
            f0 += pf[j]*sW1[j*HID + 2*c2];
            f1 += pf[j]*sW1[j*HID + 2*c2+1];
        }
        f0 = gelu(f0); f1 = gelu(f1);
        uint32_t hi = pack2(f0, f1), lo = pack2lo(f0, f1, hi);
        uint32_t bo = r*(MSTRIDE*2) + c2*4;
        *(uint32_t*)(dsm + OFF_AH + bo) = hi;
        *(uint32_t*)(dsm + OFF_AL + bo) = lo;
    }
    cp_blob(dsm + OFF_BH, g_Bsp2H, tid);
    cp_blob(dsm + OFF_BL, g_Bsp2L, tid);
    __syncthreads();
    float acc[64];
    #pragma unroll
    for (int i = 0; i < 64; i++) acc[i] = 0.f;
    gemm128(sb, OFF_AH, OFF_AL, OFF_BH, OFF_BL, acc, wid, lane);
    // ---- epilogue: gelu + split -> gmem blobs ----
    uint32_t* oH = (uint32_t*)(g_kbspH + (size_t)t*16384);
    uint32_t* oL = (uint32_t*)(g_kbspL + (size_t)t*16384);
    int row_lo = wid*16 + (lane >> 2);
    #pragma unroll
    for (int nt = 0; nt < 16; nt++) {
        int col = nt*8 + (lane & 3)*2;
        float b20 = sb2[col], b21 = sb2[col+1];
        int cp = col >> 1;
        float f0 = gelu(acc[nt*4+0] + b20), f1 = gelu(acc[nt*4+1] + b21);
        uint32_t hi = pack2(f0, f1);
        oH[row_lo*64 + cp] = hi; oL[row_lo*64 + cp] = pack2lo(f0, f1, hi);
        float f2 = gelu(acc[nt*4+2] + b20), f3 = gelu(acc[nt*4+3] + b21);
        uint32_t hi2 = pack2(f2, f3);
        oH[(row_lo+8)*64 + cp] = hi2; oL[(row_lo+8)*64 + cp] = pack2lo(f2, f3, hi2);
    }
}

__global__ void k_zero_agg() {
    size_t idx = (size_t)blockIdx.x*blockDim.x + threadIdx.x;
    if (idx < (size_t)NN*NG*HID) g_agg[idx] = 0.f;
}

// ---------------- K6: edge GEMM + scatter ----------------
__global__ void __launch_bounds__(256) k_edge(const int* __restrict__ ei, int l) {
    int t = blockIdx.x, tid = threadIdx.x;
    int wid = tid >> 5, lane = tid & 31;
    uint32_t sb = smem_u32(dsm);
    cp_blob(dsm + OFF_AH, g_kbspH + (size_t)t*16384, tid);
    cp_blob(dsm + OFF_AL, g_kbspL + (size_t)t*16384, tid);
    cp_blob(dsm + OFF_BH, g_BWkH + (size_t)l*16384, tid);
    cp_blob(dsm + OFF_BL, g_BWkL + (size_t)l*16384, tid);
    __syncthreads();
    float acc[64];
    #pragma unroll
    for (int i = 0; i < 64; i++) acc[i] = 0.f;
    gemm128(sb, OFF_AH, OFF_AL, OFF_BH, OFF_BL, acc, wid, lane);
    __syncthreads();                        // B region dead -> reuse as f32 tile
    float* tile = (float*)(dsm + OFF_BH);
    int row_lo = wid*16 + (lane >> 2);
    #pragma unroll
    for (int nt = 0; nt < 16; nt++) {
        int col = nt*8 + (lane & 3)*2;
        tile[row_lo*TSTRIDE + col]       = acc[nt*4+0];
        tile[row_lo*TSTRIDE + col+1]     = acc[nt*4+1];
        tile[(row_lo+8)*TSTRIDE + col]   = acc[nt*4+2];
        tile[(row_lo+8)*TSTRIDE + col+1] = acc[nt*4+3];
    }
    __syncthreads();
    int c = tid & 127, rb = tid >> 7;
    int base = t*128;
    for (int rr = rb; rr < 128; rr += 2) {
        int gr = base + rr, e = gr/12, p = gr - e*12;
        int sn = ei[e], rn = ei[NE + e];
        float m = tile[rr*TSTRIDE + c] * g_h[((size_t)sn*12 + p)*HID + c];
        atomicAdd(&g_agg[((size_t)rn*12 + p)*HID + c], m);
    }
}

// ---------------- K7a: conv + LN -> hn blobs ----------------
__global__ void k_node_pre(const float* __restrict__ bconv, const float* __restrict__ lng,
                           const float* __restrict__ lnb, int l) {
    int i = blockIdx.x, c = threadIdx.x;
    __shared__ float sA[NG][HID], sH[NG][HID], mu[NG], rstd[NG];
    {
        const float4* src = (const float4*)(g_agg + (size_t)i*NG*HID);
        float4* dst = (float4*)&sA[0][0];
        for (int k = c; k < NG*HID/4; k += HID) dst[k] = src[k];
    }
    __syncthreads();
    const float* fkl = g_fk + (size_t)l*NG*NG*HID;
    float bcv = bconv[l*HID + c];
    #pragma unroll
    for (int p = 0; p < NG; p++) {
        float s = 0.f;
        #pragma unroll
        for (int o = 0; o < NG; o++) s += sA[o][c]*fkl[(p*NG + o)*HID + c];
        sH[p][c] = s*(1.0f/NG) + bcv;
    }
    __syncthreads();
    if (c < NG) {
        float s = 0.f, s2 = 0.f;
        for (int k = 0; k < HID; k++) { float v = sH[c][k]; s += v; s2 += v*v; }
        float m = s/HID; mu[c] = m; rstd[c] = rsqrtf(s2/HID - m*m + 1e-5f);
    }
    __syncthreads();
    float g = lng[l*HID+c], bbv = lnb[l*HID+c];
    float hn[NG];
    #pragma unroll
    for (int p = 0; p < NG; p++) hn[p] = (sH[p][c]-mu[p])*rstd[p]*g + bbv;
    __syncthreads();
    #pragma unroll
    for (int p = 0; p < NG; p++) sH[p][c] = hn[p];
    __syncthreads();
    for (int i2 = c; i2 < NG*64; i2 += HID) {
        int p = i2 >> 6, c2 = i2 & 63;
        int gr = i*12 + p, tt = gr >> 7, rr = gr & 127;
        float f0 = sH[p][2*c2], f1 = sH[p][2*c2+1];
        uint32_t hi = pack2(f0, f1), lo = pack2lo(f0, f1, hi);
        ((uint32_t*)(g_hnH + (size_t)tt*16384))[rr*64 + c2] = hi;
        ((uint32_t*)(g_hnL + (size_t)tt*16384))[rr*64 + c2] = lo;
    }
}

// ---------------- K7b: MLP + residual + readout ----------------
__global__ void __launch_bounds__(256) k_mlp(
        const float* __restrict__ b1, const float* __restrict__ b2,
        const float* __restrict__ Wro, const float* __restrict__ bro, int l) {
    __shared__ float sWro[HID*9];
    int t = blockIdx.x, tid = threadIdx.x;
    int wid = tid >> 5, lane = tid & 31;
    uint32_t sb = smem_u32(dsm);
    for (int i = tid; i < HID*9; i += 256) sWro[i] = Wro[(size_t)l*HID*9 + i];
    cp_blob(dsm + OFF_AH, g_hnH + (size_t)t*16384, tid);
    cp_blob(dsm + OFF_AL, g_hnL + (size_t)t*16384, tid);
    int row_lo = wid*16 + (lane >> 2);
    float acc2[64];
    #pragma unroll
    for (int i = 0; i < 64; i++) acc2[i] = 0.f;
    for (int j = 0; j < 4; j++) {
        cp_blob(dsm + OFF_BH, g_BW1H + (size_t)(l*4+j)*16384, tid);
        cp_blob(dsm + OFF_BL, g_BW1L + (size_t)(l*4+j)*16384, tid);
        __syncthreads();
        float acc1[64];
        #pragma unroll
        for (int i = 0; i < 64; i++) acc1[i] = 0.f;
        gemm128(sb, OFF_AH, OFF_AL, OFF_BH, OFF_BL, acc1, wid, lane);
        // gelu + bias -> U blobs in smem (padded bf16)
        #pragma unroll
        for (int nt = 0; nt < 16; nt++) {
            int col = nt*8 + (lane & 3)*2;
            float bj0 = b1[(size_t)l*WHID + j*128 + col];
            float bj1 = b1[(size_t)l*WHID + j*128 + col+1];
            float f0 = gelu(acc1[nt*4+0] + bj0), f1 = gelu(acc1[nt*4+1] + bj1);
            uint32_t hi = pack2(f0, f1);
            uint32_t bo = row_lo*(MSTRIDE*2) + col*2;
            *(uint32_t*)(dsm + OFF_UH + bo) = hi;
            *(uint32_t*)(dsm + OFF_UL + bo) = pack2lo(f0, f1, hi);
            float f2 = gelu(acc1[nt*4+2] + bj0), f3 = gelu(acc1[nt*4+3] + bj1);
            uint32_t hi2 = pack2(f2, f3);
            uint32_t bo2 = (row_lo+8)*(MSTRIDE*2) + col*2;
            *(uint32_t*)(dsm + OFF_UH + bo2) = hi2;
            *(uint32_t*)(dsm + OFF_UL + bo2) = pack2lo(f2, f3, hi2);
        }
        __syncthreads();
        cp_blob(dsm + OFF_BH, g_BW2H + (size_t)(l*4+j)*16384, tid);
        cp_blob(dsm + OFF_BL, g_BW2L + (size_t)(l*4+j)*16384, tid);
        __syncthreads();
        gemm128(sb, OFF_UH, OFF_UL, OFF_BH, OFF_BL, acc2, wid, lane);
        __syncthreads();   // before next chunk overwrites B
    }
    // ---- final: residual + store h + readout ----
    float* tile = (float*)(dsm + OFF_BH);
    #pragma unroll
    for (int nt = 0; nt < 16; nt++) {
        int col = nt*8 + (lane & 3)*2;
        tile[row_lo*TSTRIDE + col]       = acc2[nt*4+0];
        tile[row_lo*TSTRIDE + col+1]     = acc2[nt*4+1];
        tile[(row_lo+8)*TSTRIDE + col]   = acc2[nt*4+2];
        tile[(row_lo+8)*TSTRIDE + col+1] = acc2[nt*4+3];
    }
    __syncthreads();
    {
        int r = tid >> 1, half = tid & 1;
        size_t gr = (size_t)t*128 + r;
        float ro[9];
        #pragma unroll
        for (int m = 0; m < 9; m++) ro[m] = 0.f;
        for (int k = half*64; k < half*64 + 64; k++) {
            float hnew = tile[r*TSTRIDE + k] + b2[(size_t)l*HID + k] + g_h[gr*HID + k];
            g_h[gr*HID + k] = hnew;
            #pragma unroll
            for (int m = 0; m < 9; m++) ro[m] += hnew * sWro[k*9 + m];
        }
        #pragma unroll
        for (int m = 0; m < 9; m++) ro[m] += __shfl_xor_sync(0xffffffffu, ro[m], 1);
        if (!half) {
            #pragma unroll
            for (int m = 0; m < 9; m++)
                g_readout[gr*9 + m] += (ro[m] + bro[l*9 + m]) * (1.0f/LAY);
        }
    }
}

// ---------------- final ----------------
__global__ void k_zero_out(float* out, int n) { int t = threadIdx.x; if (t < n) out[t] = 0.f; }

__global__ void k_final(const int* __restrict__ batch, float* __restrict__ out) {
    int i = blockIdx.x, t = threadIdx.x, b = batch[i];
    if (t < OUT_S) {
        float s = 0.f;
        #pragma unroll
        for (int n = 0; n < NG; n++) s += g_readout[(size_t)i*108 + n*9 + t];
        atomicAdd(&out[b*OUT_S + t], s*(1.0f/NG));
    } else if (t < OUT_S + 3) {
        int d = t - OUT_S;
        float s = 0.f;
        #pragma unroll
        for (int n = 0; n < NG; n++)
            s += g_readout[(size_t)i*108 + n*9 + 8]*g_nodegrid[i*36 + n*3 + d];
        atomicAdd(&out[BATCH*OUT_S + b*3 + d], s*(1.0f/NG));
    }
}

// ---------------- launch ----------------
extern "C" void kernel_launch(void* const* d_in, const int* in_sizes, int n_in,
                              void* d_out, int out_size) {
    const float* x     = (const float*)d_in[0];
    const float* vec   = (const float*)d_in[1];
    const float* pos   = (const float*)d_in[2];
    const float* Q     = (const float*)d_in[3];
    const float* Wsp1  = (const float*)d_in[4];
    const float* bsp1  = (const float*)d_in[5];
    const float* Wsp2  = (const float*)d_in[6];
    const float* bsp2  = (const float*)d_in[7];
    const float* Wsh1  = (const float*)d_in[8];
    const float* bsh1  = (const float*)d_in[9];
    const float* Wsh2  = (const float*)d_in[10];
    const float* bsh2  = (const float*)d_in[11];
    const float* Wemb  = (const float*)d_in[12];
    const float* Wk    = (const float*)d_in[13];
    const float* Wfk   = (const float*)d_in[14];
    const float* bconv = (const float*)d_in[15];
    const float* lng   = (const float*)d_in[16];
    const float* lnb   = (const float*)d_in[17];
    const float* W1    = (const float*)d_in[18];
    const float* b1    = (const float*)d_in[19];
    const float* W2    = (const float*)d_in[20];
    const float* b2    = (const float*)d_in[21];
    const float* Wro   = (const float*)d_in[22];
    const float* bro   = (const float*)d_in[23];
    const int*   ei    = (const int*)d_in[24];
    const int*   batch = (const int*)d_in[25];
    float* out = (float*)d_out;

    static int attr_done = 0;
    if (!attr_done) {
        cudaFuncSetAttribute(k_kbsp, cudaFuncAttributeMaxDynamicSharedMemorySize, SM_EDGE);
        cudaFuncSetAttribute(k_edge, cudaFuncAttributeMaxDynamicSharedMemorySize, SM_EDGE);
        cudaFuncSetAttribute(k_mlp,  cudaFuncAttributeMaxDynamicSharedMemorySize, SM_MLP);
        attr_done = 1;
    }
    __nv_bfloat16 *sp2H, *sp2L, *wkH, *wkL, *w1H, *w1L, *w2H, *w2L;
    cudaGetSymbolAddress((void**)&sp2H, g_Bsp2H); cudaGetSymbolAddress((void**)&sp2L, g_Bsp2L);
    cudaGetSymbolAddress((void**)&wkH,  g_BWkH);  cudaGetSymbolAddress((void**)&wkL,  g_BWkL);
    cudaGetSymbolAddress((void**)&w1H,  g_BW1H);  cudaGetSymbolAddress((void**)&w1L,  g_BW1L);
    cudaGetSymbolAddress((void**)&w2H,  g_BW2H);  cudaGetSymbolAddress((void**)&w2L,  g_BW2L);

    k_init_grid0<<<1, 32>>>();
    k_packw<<<64, 256>>>(Wsp2, sp2H, sp2L, 128, 128);
    for (int l = 0; l < LAY; l++) {
        k_packw<<<64, 256>>>(Wk + (size_t)l*16384, wkH + (size_t)l*16384, wkL + (size_t)l*16384, 128, 128);
        k_packw<<<256, 256>>>(W1 + (size_t)l*65536, w1H + (size_t)l*4*16384, w1L + (size_t)l*4*16384, 128, 512);
        k_packw<<<256, 256>>>(W2 + (size_t)l*65536, w2H + (size_t)l*4*16384, w2L + (size_t)l*4*16384, 512, 128);
    }
    k_kbsh<<<NG*NG, HID>>>(Wsh1, bsh1, Wsh2, bsh2);
    k_fk<<<LAY*NG*NG, HID>>>(Wfk);
    k_nodeinit<<<NN, HID>>>(x, vec, Q, batch, Wemb);
    k_kbsp<<<ETILES, 256, SM_EDGE>>>(pos, ei, Wsp1, bsp1, bsp2);

    for (int l = 0; l < LAY; l++) {
        k_zero_agg<<<(NN*NG*HID + 255)/256, 256>>>();
        k_edge<<<ETILES, 256, SM_EDGE>>>(ei, l);
        k_node_pre<<<NN, HID>>>(bconv, lng, lnb, l);
        k_mlp<<<NTILES, 256, SM_MLP>>>(b1, b2, Wro, bro, l);
    }
    k_zero_out<<<1, 1024>>>(out, out_size);
    k_final<<<NN, 32>>>(batch, out);
}

// round 12
// speedup vs baseline: 1.4426x; 1.4426x over previous
#include <cuda_runtime.h>
#include <cuda_bf16.h>
#include <math.h>
#include <stdint.h>

#define NN     8000
#define NE     64000
#define BATCH  64
#define NG     12
#define HID    128
#define LAY    3
#define IN_S   16
#define OUT_S  8
#define WHID   512
#define ETILES 6000   // 768000/128
#define NTILES 750    // 96000/128

// smem matrix: 128 rows x 136 bf16 (272B stride, conflict-free ldmatrix)
#define MSTRIDE   136
#define MBYTES    (128*MSTRIDE*2)   // 34816
// two-tile kernels (kbsp/edge): A0H A0L A1H A1L BH BL
#define OFF_B2H   (4*MBYTES)        // 139264
#define OFF_B2L   (5*MBYTES)        // 174080
#define SM_BIG    (6*MBYTES)        // 208896
// mlp: AH AL BH BL UH UL
#define OFF_AH    0
#define OFF_AL    34816
#define OFF_BH    69632
#define OFF_BL    104448
#define OFF_UH    139264
#define OFF_UL    174080
#define TSTRIDE   132               // f32 epilogue tile stride

// ---------------- helpers ----------------
__device__ __forceinline__ uint32_t smem_u32(const void* p) {
    uint32_t a;
    asm("{ .reg .u64 t; cvta.to.shared.u64 t, %1; cvt.u32.u64 %0, t; }" : "=r"(a) : "l"(p));
    return a;
}
__device__ __forceinline__ void ldsm4(uint32_t addr, uint32_t* r) {
    asm volatile("ldmatrix.sync.aligned.m8n8.x4.shared.b16 {%0,%1,%2,%3}, [%4];"
        : "=r"(r[0]), "=r"(r[1]), "=r"(r[2]), "=r"(r[3]) : "r"(addr));
}
__device__ __forceinline__ void mma16816(float* d, const uint32_t* a, uint32_t b0, uint32_t b1) {
    asm volatile("mma.sync.aligned.m16n8k16.row.col.f32.bf16.bf16.f32 "
        "{%0,%1,%2,%3}, {%4,%5,%6,%7}, {%8,%9}, {%0,%1,%2,%3};"
        : "+f"(d[0]), "+f"(d[1]), "+f"(d[2]), "+f"(d[3])
        : "r"(a[0]), "r"(a[1]), "r"(a[2]), "r"(a[3]), "r"(b0), "r"(b1));
}
__device__ __forceinline__ uint32_t pack2(float a, float b) {
    __nv_bfloat162 h; h.x = __float2bfloat16(a); h.y = __float2bfloat16(b);
    return *reinterpret_cast<uint32_t*>(&h);
}
__device__ __forceinline__ uint32_t pack2lo(float a, float b, uint32_t hi) {
    __nv_bfloat162 h = *reinterpret_cast<__nv_bfloat162*>(&hi);
    __nv_bfloat162 l; l.x = __float2bfloat16(a - __bfloat162float(h.x));
    l.y = __float2bfloat16(b - __bfloat162float(h.y));
    return *reinterpret_cast<uint32_t*>(&l);
}
__device__ __forceinline__ float gelu(float x) {
    return x * 0.5f * (1.0f + erff(x * 0.70710678118654752f));
}

// C[128x128] += A[128x128] @ B[n][k]^T with bf16x3 split. acc[64]: [ntile0..15][4]
__device__ __forceinline__ void gemm128(uint32_t sb, uint32_t aH, uint32_t aL,
                                        uint32_t bH, uint32_t bL,
                                        float* acc, int wid, int lane) {
    uint32_t arow  = wid*16 + (lane & 15);
    uint32_t acolo = (lane >> 4) << 3;
    uint32_t brow  = ((lane >> 4) << 3) + (lane & 7);
    uint32_t bcolo = ((lane >> 3) & 1) << 3;
    #pragma unroll
    for (int kt = 0; kt < 8; kt++) {
        uint32_t k0 = kt * 16;
        uint32_t aoff = (arow*MSTRIDE + k0 + acolo) * 2;
        uint32_t ah[4], al[4];
        ldsm4(sb + aH + aoff, ah);
        ldsm4(sb + aL + aoff, al);
        #pragma unroll
        for (int g = 0; g < 8; g++) {
            uint32_t boff = ((g*16 + brow)*MSTRIDE + k0 + bcolo) * 2;
            uint32_t bh[4], bl[4];
            ldsm4(sb + bH + boff, bh);
            ldsm4(sb + bL + boff, bl);
            float* a0 = acc + g*8;
            mma16816(a0,     ah, bh[0], bh[1]);
            mma16816(a0,     ah, bl[0], bl[1]);
            mma16816(a0,     al, bh[0], bh[1]);
            mma16816(a0 + 4, ah, bh[2], bh[3]);
            mma16816(a0 + 4, ah, bl[2], bl[3]);
            mma16816(a0 + 4, al, bh[2], bh[3]);
        }
    }
}
// copy unpadded 128x128 bf16 gmem blob -> padded smem matrix (NT = threads)
template<int NT>
__device__ __forceinline__ void cp_blob(char* dst, const __nv_bfloat16* src, int tid) {
    const uint4* s = (const uint4*)src;
    for (int i = tid; i < 2048; i += NT) {
        int row = i >> 4, j = i & 15;
        ((uint4*)dst)[row*17 + j] = s[i];
    }
}

// ---------------- device scratch ----------------
__device__ float g_grid0[NG*3];
__device__ float g_kbsh[NG*NG*HID];
__device__ float g_fk[LAY*NG*NG*HID];
__device__ float g_nodegrid[NN*NG*3];
__device__ float g_h[NN*NG*HID];
__device__ float g_agg[NN*NG*HID];
__device__ float g_readout[NN*NG*9];
__device__ __nv_bfloat16 g_kbspH[(size_t)ETILES*16384];
__device__ __nv_bfloat16 g_kbspL[(size_t)ETILES*16384];
__device__ __nv_bfloat16 g_hnH[(size_t)NTILES*16384];
__device__ __nv_bfloat16 g_hnL[(size_t)NTILES*16384];
__device__ __nv_bfloat16 g_Bsp2H[16384],   g_Bsp2L[16384];
__device__ __nv_bfloat16 g_BWkH[3*16384],  g_BWkL[3*16384];
__device__ __nv_bfloat16 g_BW1H[12*16384], g_BW1L[12*16384];
__device__ __nv_bfloat16 g_BW2H[12*16384], g_BW2L[12*16384];

extern __shared__ __align__(16) char dsm[];

// ---------------- setup ----------------
__global__ void k_init_grid0() {
    int i = threadIdx.x;
    if (i < NG) {
        float fi = (float)i;
        float theta = (6.2831853071795865f * fi) / 1.6180339887498949f;
        float z = 1.0f - (2.0f*fi + 1.0f) / (float)NG;
        float r = sqrtf(fmaxf(1.0f - z*z, 0.0f));
        g_grid0[i*3+0] = r*cosf(theta); g_grid0[i*3+1] = r*sinf(theta); g_grid0[i*3+2] = z;
    }
}

// all weight packs in ONE kernel (keeps launch #6 == k_kbsp for ncu)
__global__ void k_pack_all(const float* __restrict__ Wsp2, const float* __restrict__ Wk,
                           const float* __restrict__ W1, const float* __restrict__ W2) {
    int idx = blockIdx.x * blockDim.x + threadIdx.x;
    const float* src; __nv_bfloat16 *dh, *dl;
    int K, N, off, blobbase;
    if (idx < 16384) {                       // Wsp2 [128][128]
        src = Wsp2; dh = g_Bsp2H; dl = g_Bsp2L; K = 128; N = 128; off = idx; blobbase = 0;
    } else if (idx < 65536) {                // Wk 3x[128][128]
        int r = idx - 16384; int l = r >> 14; off = r & 16383;
        src = Wk + (size_t)l*16384; dh = g_BWkH; dl = g_BWkL; K = 128; N = 128; blobbase = l;
    } else if (idx < 262144) {               // W1 3x[128][512]
        int r = idx - 65536; int l = r >> 16; off = r & 65535;
        src = W1 + (size_t)l*65536; dh = g_BW1H; dl = g_BW1L; K = 128; N = 512; blobbase = l*4;
    } else if (idx < 458752) {               // W2 3x[512][128]
        int r = idx - 262144; int l = r >> 16; off = r & 65535;
        src = W2 + (size_t)l*65536; dh = g_BW2H; dl = g_BW2L; K = 512; N = 128; blobbase = l*4;
    } else return;
    int k = off / N, n = off % N;
    int blob = blobbase + (n >> 7) * (K >> 7) + (k >> 7);
    int o = (n & 127)*128 + (k & 127);
    float v = src[off];
    __nv_bfloat16 h = __float2bfloat16(v);
    dh[(size_t)blob*16384 + o] = h;
    dl[(size_t)blob*16384 + o] = __float2bfloat16(v - __bfloat162float(h));
}

__global__ void k_kbsh(const float* __restrict__ Wsh1, const float* __restrict__ bsh1,
                       const float* __restrict__ Wsh2, const float* __restrict__ bsh2) {
    int row = blockIdx.x, p = row/NG, o = row%NG, c = threadIdx.x;
    __shared__ float h1[HID];
    float t = g_grid0[p*3]*g_grid0[o*3] + g_grid0[p*3+1]*g_grid0[o*3+1] + g_grid0[p*3+2]*g_grid0[o*3+2];
    h1[c] = gelu(bsh1[c] + t*Wsh1[c] + t*t*Wsh1[HID+c] + t*t*t*Wsh1[2*HID+c]);
    __syncthreads();
    float acc = bsh2[c];
    #pragma unroll 8
    for (int k = 0; k < HID; k++) acc += h1[k]*Wsh2[k*HID+c];
    g_kbsh[row*HID + c] = gelu(acc);
}

__global__ void k_fk(const float* __restrict__ Wfk) {
    int blk = blockIdx.x, l = blk/(NG*NG), row = blk%(NG*NG), c = threadIdx.x;
    __shared__ float kb[HID];
    kb[c] = g_kbsh[row*HID + c];
    __syncthreads();
    const float* W = Wfk + (size_t)l*HID*HID;
    float acc = 0.f;
    #pragma unroll 8
    for (int b = 0; b < HID; b++) acc += kb[b]*W[b*HID+c];
    g_fk[((size_t)l*NG*NG + row)*HID + c] = acc;
}

__global__ void k_nodeinit(const float* __restrict__ x, const float* __restrict__ vec,
                           const float* __restrict__ Q, const int* __restrict__ batch,
                           const float* __restrict__ Wemb) {
    int i = blockIdx.x, t = threadIdx.x;
    __shared__ float ng[NG][3], xv[NG][2], xs[IN_S];
    int b = batch[i];
    if (t < 36) {
        int n = t/3, d = t%3; float s = 0.f;
        #pragma unroll
        for (int j = 0; j < 3; j++) s += Q[b*9 + d*3 + j]*g_grid0[n*3+j];
        ng[n][d] = s; g_nodegrid[i*36 + t] = s;
    }
    if (t >= 64 && t < 64+IN_S) xs[t-64] = x[i*IN_S + (t-64)];
    if (t < 108) g_readout[(size_t)i*108 + t] = 0.f;
    __syncthreads();
    if (t < 24) {
        int n = t/2, v = t%2;
        xv[n][v] = vec[i*6+v*3]*ng[n][0] + vec[i*6+v*3+1]*ng[n][1] + vec[i*6+v*3+2]*ng[n][2];
    }
    __syncthreads();
    int c = t; float hx = 0.f;
    #pragma unroll
    for (int s = 0; s < IN_S; s++) hx += xs[s]*Wemb[s*HID+c];
    float w16 = Wemb[16*HID+c], w17 = Wemb[17*HID+c];
    #pragma unroll
    for (int n = 0; n < NG; n++)
        g_h[(size_t)i*NG*HID + n*HID + c] = hx + xv[n][0]*w16 + xv[n][1]*w17;
}

// ---------------- K4: kbsp — 2 tiles per block, 512 threads ----------------
__global__ void __launch_bounds__(512) k_kbsp(
        const float* __restrict__ pos, const int* __restrict__ ei,
        const float* __restrict__ Wsp1, const float* __restrict__ bsp1,
        const float* __restrict__ bsp2) {
    __shared__ float sW1[14*HID], sb1[HID], sb2[HID];
    int blk = blockIdx.x, tid = threadIdx.x;
    int wid = tid >> 5, lane = tid & 31;
    for (int i = tid; i < 14*HID; i += 512) sW1[i] = Wsp1[i];
    if (tid < HID) { sb1[tid] = bsp1[tid]; sb2[tid] = bsp2[tid]; }
    uint32_t sb = smem_u32(dsm);
    // ---- front: h1 rows 0..255 -> A0/A1 blobs (hi/lo) ----
    int r = tid >> 1, half = tid & 1;            // r in 0..255
    int gr = blk*256 + r, e = gr/12, p = gr - e*12;
    int sn = ei[e], rn = ei[NE + e];
    float rx = pos[sn*3]-pos[rn*3], ry = pos[sn*3+1]-pos[rn*3+1], rz = pos[sn*3+2]-pos[rn*3+2];
    float gx = g_nodegrid[rn*36+p*3], gy = g_nodegrid[rn*36+p*3+1], gz = g_nodegrid[rn*36+p*3+2];
    float a = rx*gx + ry*gy + rz*gz;
    float vx = rx-a*gx, vy = ry-a*gy, vz = rz-a*gz;
    float bb = sqrtf(vx*vx + vy*vy + vz*vz);
    float pf[14] = {a, bb, a*a, a*bb, bb*a, bb*bb, a*a*a, a*a*bb, a*bb*a, a*bb*bb,
                    bb*a*a, bb*a*bb, bb*bb*a, bb*bb*bb};
    __syncthreads();   // sW1/sb1 ready
    {
        uint32_t aBase = (uint32_t)(r >> 7) * (2*MBYTES);
        int rr = r & 127;
        for (int c2 = half*32; c2 < half*32 + 32; c2++) {
            float f0 = sb1[2*c2], f1 = sb1[2*c2+1];
            #pragma unroll
            for (int j = 0; j < 14; j++) {
                f0 += pf[j]*sW1[j*HID + 2*c2];
                f1 += pf[j]*sW1[j*HID + 2*c2+1];
            }
            f0 = gelu(f0); f1 = gelu(f1);
            uint32_t hi = pack2(f0, f1), lo = pack2lo(f0, f1, hi);
            uint32_t bo = rr*(MSTRIDE*2) + c2*4;
            *(uint32_t*)(dsm + aBase + bo) = hi;
            *(uint32_t*)(dsm + aBase + MBYTES + bo) = lo;
        }
    }
    cp_blob<512>(dsm + OFF_B2H, g_Bsp2H, tid);
    cp_blob<512>(dsm + OFF_B2L, g_Bsp2L, tid);
    __syncthreads();
    float acc[64];
    #pragma unroll
    for (int i = 0; i < 64; i++) acc[i] = 0.f;
    uint32_t aOff = (uint32_t)(wid >> 3) * (2*MBYTES);
    gemm128(sb, aOff, aOff + MBYTES, OFF_B2H, OFF_B2L, acc, wid & 7, lane);
    // ---- epilogue: gelu + split -> gmem blobs ----
    int t = blk*2 + (wid >> 3);
    uint32_t* oH = (uint32_t*)(g_kbspH + (size_t)t*16384);
    uint32_t* oL = (uint32_t*)(g_kbspL + (size_t)t*16384);
    int row_lo = (wid & 7)*16 + (lane >> 2);
    #pragma unroll
    for (int nt = 0; nt < 16; nt++) {
        int col = nt*8 + (lane & 3)*2;
        float b20 = sb2[col], b21 = sb2[col+1];
        int cp = col >> 1;
        float f0 = gelu(acc[nt*4+0] + b20), f1 = gelu(acc[nt*4+1] + b21);
        uint32_t hi = pack2(f0, f1);
        oH[row_lo*64 + cp] = hi; oL[row_lo*64 + cp] = pack2lo(f0, f1, hi);
        float f2 = gelu(acc[nt*4+2] + b20), f3 = gelu(acc[nt*4+3] + b21);
        uint32_t hi2 = pack2(f2, f3);
        oH[(row_lo+8)*64 + cp] = hi2; oL[(row_lo+8)*64 + cp] = pack2lo(f2, f3, hi2);
    }
}

__global__ void k_zero_agg() {
    size_t idx = (size_t)blockIdx.x*blockDim.x + threadIdx.x;
    if (idx < (size_t)NN*NG*HID) g_agg[idx] = 0.f;
}

// ---------------- K6: edge GEMM + scatter — 2 tiles, 512 threads ----------------
__global__ void __launch_bounds__(512) k_edge(const int* __restrict__ ei, int l) {
    int blk = blockIdx.x, tid = threadIdx.x;
    int wid = tid >> 5, lane = tid & 31;
    uint32_t sb = smem_u32(dsm);
    cp_blob<512>(dsm,            g_kbspH + (size_t)(2*blk)*16384, tid);
    cp_blob<512>(dsm + MBYTES,   g_kbspL + (size_t)(2*blk)*16384, tid);
    cp_blob<512>(dsm + 2*MBYTES, g_kbspH + (size_t)(2*blk+1)*16384, tid);
    cp_blob<512>(dsm + 3*MBYTES, g_kbspL + (size_t)(2*blk+1)*16384, tid);
    cp_blob<512>(dsm + OFF_B2H,  g_BWkH + (size_t)l*16384, tid);
    cp_blob<512>(dsm + OFF_B2L,  g_BWkL + (size_t)l*16384, tid);
    __syncthreads();
    float acc[64];
    #pragma unroll
    for (int i = 0; i < 64; i++) acc[i] = 0.f;
    uint32_t aOff = (uint32_t)(wid >> 3) * (2*MBYTES);
    gemm128(sb, aOff, aOff + MBYTES, OFF_B2H, OFF_B2L, acc, wid & 7, lane);
    __syncthreads();                        // B region dead -> staging
    float* stage = (float*)(dsm + OFF_B2H);
    int row_lo = (wid & 7)*16 + (lane >> 2);
    for (int tp = 0; tp < 2; tp++) {
        if ((wid >> 3) == tp) {
            #pragma unroll
            for (int nt = 0; nt < 16; nt++) {
                int col = nt*8 + (lane & 3)*2;
                stage[row_lo*TSTRIDE + col]       = acc[nt*4+0];
                stage[row_lo*TSTRIDE + col+1]     = acc[nt*4+1];
                stage[(row_lo+8)*TSTRIDE + col]   = acc[nt*4+2];
                stage[(row_lo+8)*TSTRIDE + col+1] = acc[nt*4+3];
            }
        }
        __syncthreads();
        int c = tid & 127, rb = tid >> 7;
        int base = blk*256 + tp*128;
        for (int rr = rb; rr < 128; rr += 4) {
            int gr = base + rr, e = gr/12, p = gr - e*12;
            int sn = ei[e], rn = ei[NE + e];
            float m = stage[rr*TSTRIDE + c] * g_h[((size_t)sn*12 + p)*HID + c];
            atomicAdd(&g_agg[((size_t)rn*12 + p)*HID + c], m);
        }
        __syncthreads();
    }
}

// ---------------- K7a: conv + LN -> hn blobs ----------------
__global__ void k_node_pre(const float* __restrict__ bconv, const float* __restrict__ lng,
                           const float* __restrict__ lnb, int l) {
    int i = blockIdx.x, c = threadIdx.x;
    __shared__ float sA[NG][HID], sH[NG][HID], mu[NG], rstd[NG];
    {
        const float4* src = (const float4*)(g_agg + (size_t)i*NG*HID);
        float4* dst = (float4*)&sA[0][0];
        for (int k = c; k < NG*HID/4; k += HID) dst[k] = src[k];
    }
    __syncthreads();
    const float* fkl = g_fk + (size_t)l*NG*NG*HID;
    float bcv = bconv[l*HID + c];
    #pragma unroll
    for (int p = 0; p < NG; p++) {
        float s = 0.f;
        #pragma unroll
        for (int o = 0; o < NG; o++) s += sA[o][c]*fkl[(p*NG + o)*HID + c];
        sH[p][c] = s*(1.0f/NG) + bcv;
    }
    __syncthreads();
    if (c < NG) {
        float s = 0.f, s2 = 0.f;
        for (int k = 0; k < HID; k++) { float v = sH[c][k]; s += v; s2 += v*v; }
        float m = s/HID; mu[c] = m; rstd[c] = rsqrtf(s2/HID - m*m + 1e-5f);
    }
    __syncthreads();
    float g = lng[l*HID+c], bbv = lnb[l*HID+c];
    float hn[NG];
    #pragma unroll
    for (int p = 0; p < NG; p++) hn[p] = (sH[p][c]-mu[p])*rstd[p]*g + bbv;
    __syncthreads();
    #pragma unroll
    for (int p = 0; p < NG; p++) sH[p][c] = hn[p];
    __syncthreads();
    for (int i2 = c; i2 < NG*64; i2 += HID) {
        int p = i2 >> 6, c2 = i2 & 63;
        int gr = i*12 + p, tt = gr >> 7, rr = gr & 127;
        float f0 = sH[p][2*c2], f1 = sH[p][2*c2+1];
        uint32_t hi = pack2(f0, f1), lo = pack2lo(f0, f1, hi);
        ((uint32_t*)(g_hnH + (size_t)tt*16384))[rr*64 + c2] = hi;
        ((uint32_t*)(g_hnL + (size_t)tt*16384))[rr*64 + c2] = lo;
    }
}

// ---------------- K7b: MLP + residual + readout ----------------
__global__ void __launch_bounds__(256) k_mlp(
        const float* __restrict__ b1, const float* __restrict__ b2,
        const float* __restrict__ Wro, const float* __restrict__ bro, int l) {
    __shared__ float sWro[HID*9];
    int t = blockIdx.x, tid = threadIdx.x;
    int wid = tid >> 5, lane = tid & 31;
    uint32_t sb = smem_u32(dsm);
    for (int i = tid; i < HID*9; i += 256) sWro[i] = Wro[(size_t)l*HID*9 + i];
    cp_blob<256>(dsm + OFF_AH, g_hnH + (size_t)t*16384, tid);
    cp_blob<256>(dsm + OFF_AL, g_hnL + (size_t)t*16384, tid);
    int row_lo = wid*16 + (lane >> 2);
    float acc2[64];
    #pragma unroll
    for (int i = 0; i < 64; i++) acc2[i] = 0.f;
    for (int j = 0; j < 4; j++) {
        cp_blob<256>(dsm + OFF_BH, g_BW1H + (size_t)(l*4+j)*16384, tid);
        cp_blob<256>(dsm + OFF_BL, g_BW1L + (size_t)(l*4+j)*16384, tid);
        __syncthreads();
        float acc1[64];
        #pragma unroll
        for (int i = 0; i < 64; i++) acc1[i] = 0.f;
        gemm128(sb, OFF_AH, OFF_AL, OFF_BH, OFF_BL, acc1, wid, lane);
        #pragma unroll
        for (int nt = 0; nt < 16; nt++) {
            int col = nt*8 + (lane & 3)*2;
            float bj0 = b1[(size_t)l*WHID + j*128 + col];
            float bj1 = b1[(size_t)l*WHID + j*128 + col+1];
            float f0 = gelu(acc1[nt*4+0] + bj0), f1 = gelu(acc1[nt*4+1] + bj1);
            uint32_t hi = pack2(f0, f1);
            uint32_t bo = row_lo*(MSTRIDE*2) + col*2;
            *(uint32_t*)(dsm + OFF_UH + bo) = hi;
            *(uint32_t*)(dsm + OFF_UL + bo) = pack2lo(f0, f1, hi);
            float f2 = gelu(acc1[nt*4+2] + bj0), f3 = gelu(acc1[nt*4+3] + bj1);
            uint32_t hi2 = pack2(f2, f3);
            uint32_t bo2 = (row_lo+8)*(MSTRIDE*2) + col*2;
            *(uint32_t*)(dsm + OFF_UH + bo2) = hi2;
            *(uint32_t*)(dsm + OFF_UL + bo2) = pack2lo(f2, f3, hi2);
        }
        __syncthreads();
        cp_blob<256>(dsm + OFF_BH, g_BW2H + (size_t)(l*4+j)*16384, tid);
        cp_blob<256>(dsm + OFF_BL, g_BW2L + (size_t)(l*4+j)*16384, tid);
        __syncthreads();
        gemm128(sb, OFF_UH, OFF_UL, OFF_BH, OFF_BL, acc2, wid, lane);
        __syncthreads();
    }
    float* tile = (float*)(dsm + OFF_BH);
    #pragma unroll
    for (int nt = 0; nt < 16; nt++) {
        int col = nt*8 + (lane & 3)*2;
        tile[row_lo*TSTRIDE + col]       = acc2[nt*4+0];
        tile[row_lo*TSTRIDE + col+1]     = acc2[nt*4+1];
        tile[(row_lo+8)*TSTRIDE + col]   = acc2[nt*4+2];
        tile[(row_lo+8)*TSTRIDE + col+1] = acc2[nt*4+3];
    }
    __syncthreads();
    {
        int r = tid >> 1, half = tid & 1;
        size_t gr = (size_t)t*128 + r;
        float ro[9];
        #pragma unroll
        for (int m = 0; m < 9; m++) ro[m] = 0.f;
        for (int k = half*64; k < half*64 + 64; k++) {
            float hnew = tile[r*TSTRIDE + k] + b2[(size_t)l*HID + k] + g_h[gr*HID + k];
            g_h[gr*HID + k] = hnew;
            #pragma unroll
            for (int m = 0; m < 9; m++) ro[m] += hnew * sWro[k*9 + m];
        }
        #pragma unroll
        for (int m = 0; m < 9; m++) ro[m] += __shfl_xor_sync(0xffffffffu, ro[m], 1);
        if (!half) {
            #pragma unroll
            for (int m = 0; m < 9; m++)
                g_readout[gr*9 + m] += (ro[m] + bro[l*9 + m]) * (1.0f/LAY);
        }
    }
}

// ---------------- final ----------------
__global__ void k_zero_out(float* out, int n) { int t = threadIdx.x; if (t < n) out[t] = 0.f; }

__global__ void k_final(const int* __restrict__ batch, float* __restrict__ out) {
    int i = blockIdx.x, t = threadIdx.x, b = batch[i];
    if (t < OUT_S) {
        float s = 0.f;
        #pragma unroll
        for (int n = 0; n < NG; n++) s += g_readout[(size_t)i*108 + n*9 + t];
        atomicAdd(&out[b*OUT_S + t], s*(1.0f/NG));
    } else if (t < OUT_S + 3) {
        int d = t - OUT_S;
        float s = 0.f;
        #pragma unroll
        for (int n = 0; n < NG; n++)
            s += g_readout[(size_t)i*108 + n*9 + 8]*g_nodegrid[i*36 + n*3 + d];
        atomicAdd(&out[BATCH*OUT_S + b*3 + d], s*(1.0f/NG));
    }
}

// ---------------- launch ----------------
extern "C" void kernel_launch(void* const* d_in, const int* in_sizes, int n_in,
                              void* d_out, int out_size) {
    const float* x     = (const float*)d_in[0];
    const float* vec   = (const float*)d_in[1];
    const float* pos   = (const float*)d_in[2];
    const float* Q     = (const float*)d_in[3];
    const float* Wsp1  = (const float*)d_in[4];
    const float* bsp1  = (const float*)d_in[5];
    const float* Wsp2  = (const float*)d_in[6];
    const float* bsp2  = (const float*)d_in[7];
    const float* Wsh1  = (const float*)d_in[8];
    const float* bsh1  = (const float*)d_in[9];
    const float* Wsh2  = (const float*)d_in[10];
    const float* bsh2  = (const float*)d_in[11];
    const float* Wemb  = (const float*)d_in[12];
    const float* Wk    = (const float*)d_in[13];
    const float* Wfk   = (const float*)d_in[14];
    const float* bconv = (const float*)d_in[15];
    const float* lng   = (const float*)d_in[16];
    const float* lnb   = (const float*)d_in[17];
    const float* W1    = (const float*)d_in[18];
    const float* b1    = (const float*)d_in[19];
    const float* W2    = (const float*)d_in[20];
    const float* b2    = (const float*)d_in[21];
    const float* Wro   = (const float*)d_in[22];
    const float* bro   = (const float*)d_in[23];
    const int*   ei    = (const int*)d_in[24];
    const int*   batch = (const int*)d_in[25];
    float* out = (float*)d_out;

    static int attr_done = 0;
    if (!attr_done) {
        cudaFuncSetAttribute(k_kbsp, cudaFuncAttributeMaxDynamicSharedMemorySize, SM_BIG);
        cudaFuncSetAttribute(k_edge, cudaFuncAttributeMaxDynamicSharedMemorySize, SM_BIG);
        cudaFuncSetAttribute(k_mlp,  cudaFuncAttributeMaxDynamicSharedMemorySize, SM_BIG);
        attr_done = 1;
    }

    // launch order chosen so ncu (-s 5 -c 1) captures k_kbsp (launch #6)
    k_init_grid0<<<1, 32>>>();                                   // 1
    k_pack_all<<<(458752 + 255)/256, 256>>>(Wsp2, Wk, W1, W2);   // 2
    k_kbsh<<<NG*NG, HID>>>(Wsh1, bsh1, Wsh2, bsh2);              // 3
    k_fk<<<LAY*NG*NG, HID>>>(Wfk);                               // 4
    k_nodeinit<<<NN, HID>>>(x, vec, Q, batch, Wemb);             // 5
    k_kbsp<<<ETILES/2, 512, SM_BIG>>>(pos, ei, Wsp1, bsp1, bsp2);// 6 <- profiled

    for (int l = 0; l < LAY; l++) {
        k_zero_agg<<<(NN*NG*HID + 255)/256, 256>>>();
        k_edge<<<ETILES/2, 512, SM_BIG>>>(ei, l);
        k_node_pre<<<NN, HID>>>(bconv, lng, lnb, l);
        k_mlp<<<NTILES, 256, SM_BIG>>>(b1, b2, Wro, bro, l);
    }
    k_zero_out<<<1, 1024>>>(out, out_size);
    k_final<<<NN, 32>>>(batch, out);
}

// round 13
// speedup vs baseline: 1.6056x; 1.1129x over previous
#include <cuda_runtime.h>
#include <cuda_bf16.h>
#include <math.h>
#include <stdint.h>

#define NN     8000
#define NE     64000
#define BATCH  64
#define NG     12
#define HID    128
#define LAY    3
#define IN_S   16
#define OUT_S  8
#define WHID   512
#define ETILES 6000   // 768000/128
#define NTILES 750    // 96000/128

// smem matrix: 128 rows x 136 bf16 (272B stride, conflict-free ldmatrix)
#define MSTRIDE   136
#define MBYTES    (128*MSTRIDE*2)   // 34816
// two-tile kernels (kbsp/edge): A0H A0L A1H A1L BH BL
#define OFF_B2H   (4*MBYTES)        // 139264
#define OFF_B2L   (5*MBYTES)        // 174080
#define SM_BIG    (6*MBYTES)        // 208896
// mlp: AH AL BH BL UH UL
#define OFF_AH    0
#define OFF_AL    34816
#define OFF_BH    69632
#define OFF_BL    104448
#define OFF_UH    139264
#define OFF_UL    174080
#define TSTRIDE   132               // f32 epilogue tile stride

// ---------------- helpers ----------------
__device__ __forceinline__ uint32_t smem_u32(const void* p) {
    uint32_t a;
    asm("{ .reg .u64 t; cvta.to.shared.u64 t, %1; cvt.u32.u64 %0, t; }" : "=r"(a) : "l"(p));
    return a;
}
__device__ __forceinline__ void ldsm4(uint32_t addr, uint32_t* r) {
    asm volatile("ldmatrix.sync.aligned.m8n8.x4.shared.b16 {%0,%1,%2,%3}, [%4];"
        : "=r"(r[0]), "=r"(r[1]), "=r"(r[2]), "=r"(r[3]) : "r"(addr));
}
__device__ __forceinline__ void mma16816(float* d, const uint32_t* a, uint32_t b0, uint32_t b1) {
    asm volatile("mma.sync.aligned.m16n8k16.row.col.f32.bf16.bf16.f32 "
        "{%0,%1,%2,%3}, {%4,%5,%6,%7}, {%8,%9}, {%0,%1,%2,%3};"
        : "+f"(d[0]), "+f"(d[1]), "+f"(d[2]), "+f"(d[3])
        : "r"(a[0]), "r"(a[1]), "r"(a[2]), "r"(a[3]), "r"(b0), "r"(b1));
}
__device__ __forceinline__ uint32_t pack2(float a, float b) {
    __nv_bfloat162 h; h.x = __float2bfloat16(a); h.y = __float2bfloat16(b);
    return *reinterpret_cast<uint32_t*>(&h);
}
__device__ __forceinline__ uint32_t pack2lo(float a, float b, uint32_t hi) {
    __nv_bfloat162 h = *reinterpret_cast<__nv_bfloat162*>(&hi);
    __nv_bfloat162 l; l.x = __float2bfloat16(a - __bfloat162float(h.x));
    l.y = __float2bfloat16(b - __bfloat162float(h.y));
    return *reinterpret_cast<uint32_t*>(&l);
}
__device__ __forceinline__ float gelu(float x) {
    return x * 0.5f * (1.0f + erff(x * 0.70710678118654752f));
}

// cp.async 16B copies of a 128x128 bf16 gmem blob -> padded smem matrix
template<int NT>
__device__ __forceinline__ void cp_blob_a(uint32_t dst, const __nv_bfloat16* src, int tid) {
    for (int i = tid; i < 2048; i += NT) {
        int row = i >> 4, j = i & 15;
        asm volatile("cp.async.cg.shared.global [%0], [%1], 16;"
            :: "r"(dst + (uint32_t)(row*17 + j)*16), "l"((const char*)src + (size_t)i*16));
    }
}
#define CPA_COMMIT() asm volatile("cp.async.commit_group;" ::: "memory")
#define CPA_WAIT0()  asm volatile("cp.async.wait_group 0;" ::: "memory")

// full-N gemm: warp computes rows [wid*16,+16) x cols 0..127, acc[64]
__device__ __forceinline__ void gemm128(uint32_t sb, uint32_t aH, uint32_t aL,
                                        uint32_t bH, uint32_t bL,
                                        float* acc, int wid, int lane) {
    uint32_t arow  = wid*16 + (lane & 15);
    uint32_t acolo = (lane >> 4) << 3;
    uint32_t brow  = ((lane >> 4) << 3) + (lane & 7);
    uint32_t bcolo = ((lane >> 3) & 1) << 3;
    #pragma unroll
    for (int kt = 0; kt < 8; kt++) {
        uint32_t k0 = kt * 16;
        uint32_t aoff = (arow*MSTRIDE + k0 + acolo) * 2;
        uint32_t ah[4], al[4];
        ldsm4(sb + aH + aoff, ah);
        ldsm4(sb + aL + aoff, al);
        #pragma unroll
        for (int g = 0; g < 8; g++) {
            uint32_t boff = ((g*16 + brow)*MSTRIDE + k0 + bcolo) * 2;
            uint32_t bh[4], bl[4];
            ldsm4(sb + bH + boff, bh);
            ldsm4(sb + bL + boff, bl);
            float* a0 = acc + g*8;
            mma16816(a0,     ah, bh[0], bh[1]);
            mma16816(a0,     ah, bl[0], bl[1]);
            mma16816(a0,     al, bh[0], bh[1]);
            mma16816(a0 + 4, ah, bh[2], bh[3]);
            mma16816(a0 + 4, ah, bl[2], bl[3]);
            mma16816(a0 + 4, al, bh[2], bh[3]);
        }
    }
}
// half-N gemm: warp computes rows [rowgrp*16,+16) x cols [colgrp*64,+64), acc[32]
__device__ __forceinline__ void gemm128h(uint32_t sb, uint32_t aH, uint32_t aL,
                                         uint32_t bH, uint32_t bL,
                                         float* acc, int rowgrp, int colgrp, int lane) {
    uint32_t arow  = rowgrp*16 + (lane & 15);
    uint32_t acolo = (lane >> 4) << 3;
    uint32_t brow  = ((lane >> 4) << 3) + (lane & 7);
    uint32_t bcolo = ((lane >> 3) & 1) << 3;
    #pragma unroll
    for (int kt = 0; kt < 8; kt++) {
        uint32_t k0 = kt * 16;
        uint32_t aoff = (arow*MSTRIDE + k0 + acolo) * 2;
        uint32_t ah[4], al[4];
        ldsm4(sb + aH + aoff, ah);
        ldsm4(sb + aL + aoff, al);
        #pragma unroll
        for (int g = 0; g < 4; g++) {
            uint32_t boff = (((colgrp*64 + g*16) + brow)*MSTRIDE + k0 + bcolo) * 2;
            uint32_t bh[4], bl[4];
            ldsm4(sb + bH + boff, bh);
            ldsm4(sb + bL + boff, bl);
            float* a0 = acc + g*8;
            mma16816(a0,     ah, bh[0], bh[1]);
            mma16816(a0,     ah, bl[0], bl[1]);
            mma16816(a0,     al, bh[0], bh[1]);
            mma16816(a0 + 4, ah, bh[2], bh[3]);
            mma16816(a0 + 4, ah, bl[2], bl[3]);
            mma16816(a0 + 4, al, bh[2], bh[3]);
        }
    }
}

// ---------------- device scratch ----------------
__device__ float g_grid0[NG*3];
__device__ float g_kbsh[NG*NG*HID];
__device__ float g_fk[LAY*NG*NG*HID];
__device__ float g_nodegrid[NN*NG*3];
__device__ float g_h[NN*NG*HID];
__device__ float g_agg[NN*NG*HID];
__device__ float g_readout[NN*NG*9];
__device__ __nv_bfloat16 g_kbspH[(size_t)ETILES*16384];
__device__ __nv_bfloat16 g_kbspL[(size_t)ETILES*16384];
__device__ __nv_bfloat16 g_hnH[(size_t)NTILES*16384];
__device__ __nv_bfloat16 g_hnL[(size_t)NTILES*16384];
__device__ __nv_bfloat16 g_Bsp2H[16384],   g_Bsp2L[16384];
__device__ __nv_bfloat16 g_BWkH[3*16384],  g_BWkL[3*16384];
__device__ __nv_bfloat16 g_BW1H[12*16384], g_BW1L[12*16384];
__device__ __nv_bfloat16 g_BW2H[12*16384], g_BW2L[12*16384];

extern __shared__ __align__(16) char dsm[];

// ---------------- setup ----------------
__global__ void k_init_grid0() {
    int i = threadIdx.x;
    if (i < NG) {
        float fi = (float)i;
        float theta = (6.2831853071795865f * fi) / 1.6180339887498949f;
        float z = 1.0f - (2.0f*fi + 1.0f) / (float)NG;
        float r = sqrtf(fmaxf(1.0f - z*z, 0.0f));
        g_grid0[i*3+0] = r*cosf(theta); g_grid0[i*3+1] = r*sinf(theta); g_grid0[i*3+2] = z;
    }
}

__global__ void k_pack_all(const float* __restrict__ Wsp2, const float* __restrict__ Wk,
                           const float* __restrict__ W1, const float* __restrict__ W2) {
    int idx = blockIdx.x * blockDim.x + threadIdx.x;
    const float* src; __nv_bfloat16 *dh, *dl;
    int K, N, off, blobbase;
    if (idx < 16384) {
        src = Wsp2; dh = g_Bsp2H; dl = g_Bsp2L; K = 128; N = 128; off = idx; blobbase = 0;
    } else if (idx < 65536) {
        int r = idx - 16384; int l = r >> 14; off = r & 16383;
        src = Wk + (size_t)l*16384; dh = g_BWkH; dl = g_BWkL; K = 128; N = 128; blobbase = l;
    } else if (idx < 262144) {
        int r = idx - 65536; int l = r >> 16; off = r & 65535;
        src = W1 + (size_t)l*65536; dh = g_BW1H; dl = g_BW1L; K = 128; N = 512; blobbase = l*4;
    } else if (idx < 458752) {
        int r = idx - 262144; int l = r >> 16; off = r & 65535;
        src = W2 + (size_t)l*65536; dh = g_BW2H; dl = g_BW2L; K = 512; N = 128; blobbase = l*4;
    } else return;
    int k = off / N, n = off % N;
    int blob = blobbase + (n >> 7) * (K >> 7) + (k >> 7);
    int o = (n & 127)*128 + (k & 127);
    float v = src[off];
    __nv_bfloat16 h = __float2bfloat16(v);
    dh[(size_t)blob*16384 + o] = h;
    dl[(size_t)blob*16384 + o] = __float2bfloat16(v - __bfloat162float(h));
}

__global__ void k_kbsh(const float* __restrict__ Wsh1, const float* __restrict__ bsh1,
                       const float* __restrict__ Wsh2, const float* __restrict__ bsh2) {
    int row = blockIdx.x, p = row/NG, o = row%NG, c = threadIdx.x;
    __shared__ float h1[HID];
    float t = g_grid0[p*3]*g_grid0[o*3] + g_grid0[p*3+1]*g_grid0[o*3+1] + g_grid0[p*3+2]*g_grid0[o*3+2];
    h1[c] = gelu(bsh1[c] + t*Wsh1[c] + t*t*Wsh1[HID+c] + t*t*t*Wsh1[2*HID+c]);
    __syncthreads();
    float acc = bsh2[c];
    #pragma unroll 8
    for (int k = 0; k < HID; k++) acc += h1[k]*Wsh2[k*HID+c];
    g_kbsh[row*HID + c] = gelu(acc);
}

__global__ void k_fk(const float* __restrict__ Wfk) {
    int blk = blockIdx.x, l = blk/(NG*NG), row = blk%(NG*NG), c = threadIdx.x;
    __shared__ float kb[HID];
    kb[c] = g_kbsh[row*HID + c];
    __syncthreads();
    const float* W = Wfk + (size_t)l*HID*HID;
    float acc = 0.f;
    #pragma unroll 8
    for (int b = 0; b < HID; b++) acc += kb[b]*W[b*HID+c];
    g_fk[((size_t)l*NG*NG + row)*HID + c] = acc;
}

__global__ void k_nodeinit(const float* __restrict__ x, const float* __restrict__ vec,
                           const float* __restrict__ Q, const int* __restrict__ batch,
                           const float* __restrict__ Wemb) {
    int i = blockIdx.x, t = threadIdx.x;
    __shared__ float ng[NG][3], xv[NG][2], xs[IN_S];
    int b = batch[i];
    if (t < 36) {
        int n = t/3, d = t%3; float s = 0.f;
        #pragma unroll
        for (int j = 0; j < 3; j++) s += Q[b*9 + d*3 + j]*g_grid0[n*3+j];
        ng[n][d] = s; g_nodegrid[i*36 + t] = s;
    }
    if (t >= 64 && t < 64+IN_S) xs[t-64] = x[i*IN_S + (t-64)];
    if (t < 108) g_readout[(size_t)i*108 + t] = 0.f;
    __syncthreads();
    if (t < 24) {
        int n = t/2, v = t%2;
        xv[n][v] = vec[i*6+v*3]*ng[n][0] + vec[i*6+v*3+1]*ng[n][1] + vec[i*6+v*3+2]*ng[n][2];
    }
    __syncthreads();
    int c = t; float hx = 0.f;
    #pragma unroll
    for (int s = 0; s < IN_S; s++) hx += xs[s]*Wemb[s*HID+c];
    float w16 = Wemb[16*HID+c], w17 = Wemb[17*HID+c];
    #pragma unroll
    for (int n = 0; n < NG; n++)
        g_h[(size_t)i*NG*HID + n*HID + c] = hx + xv[n][0]*w16 + xv[n][1]*w17;
}

// ---------------- K4: kbsp — 2 tiles per block, 512 threads ----------------
__global__ void __launch_bounds__(512) k_kbsp(
        const float* __restrict__ pos, const int* __restrict__ ei,
        const float* __restrict__ Wsp1, const float* __restrict__ bsp1,
        const float* __restrict__ bsp2) {
    __shared__ float sW1[14*HID], sb1[HID], sb2[HID];
    int blk = blockIdx.x, tid = threadIdx.x;
    int wid = tid >> 5, lane = tid & 31;
    uint32_t sb = smem_u32(dsm);
    // B operand copies overlap the SIMT front below
    cp_blob_a<512>(sb + OFF_B2H, g_Bsp2H, tid);
    cp_blob_a<512>(sb + OFF_B2L, g_Bsp2L, tid);
    CPA_COMMIT();
    for (int i = tid; i < 14*HID; i += 512) sW1[i] = Wsp1[i];
    if (tid < HID) { sb1[tid] = bsp1[tid]; sb2[tid] = bsp2[tid]; }
    // ---- front: h1 rows 0..255 -> A0/A1 blobs (hi/lo) ----
    int r = tid >> 1, half = tid & 1;            // r in 0..255
    int gr = blk*256 + r, e = gr/12, p = gr - e*12;
    int sn = ei[e], rn = ei[NE + e];
    float rx = pos[sn*3]-pos[rn*3], ry = pos[sn*3+1]-pos[rn*3+1], rz = pos[sn*3+2]-pos[rn*3+2];
    float gx = g_nodegrid[rn*36+p*3], gy = g_nodegrid[rn*36+p*3+1], gz = g_nodegrid[rn*36+p*3+2];
    float a = rx*gx + ry*gy + rz*gz;
    float vx = rx-a*gx, vy = ry-a*gy, vz = rz-a*gz;
    float bb = sqrtf(vx*vx + vy*vy + vz*vz);
    float pf[14] = {a, bb, a*a, a*bb, bb*a, bb*bb, a*a*a, a*a*bb, a*bb*a, a*bb*bb,
                    bb*a*a, bb*a*bb, bb*bb*a, bb*bb*bb};
    __syncthreads();   // sW1/sb1 ready
    {
        uint32_t aBase = (uint32_t)(r >> 7) * (2*MBYTES);
        int rr = r & 127;
        for (int c2 = half*32; c2 < half*32 + 32; c2++) {
            float f0 = sb1[2*c2], f1 = sb1[2*c2+1];
            #pragma unroll
            for (int j = 0; j < 14; j++) {
                f0 += pf[j]*sW1[j*HID + 2*c2];
                f1 += pf[j]*sW1[j*HID + 2*c2+1];
            }
            f0 = gelu(f0); f1 = gelu(f1);
            uint32_t hi = pack2(f0, f1), lo = pack2lo(f0, f1, hi);
            uint32_t bo = rr*(MSTRIDE*2) + c2*4;
            *(uint32_t*)(dsm + aBase + bo) = hi;
            *(uint32_t*)(dsm + aBase + MBYTES + bo) = lo;
        }
    }
    CPA_WAIT0();
    __syncthreads();
    float acc[64];
    #pragma unroll
    for (int i = 0; i < 64; i++) acc[i] = 0.f;
    uint32_t aOff = (uint32_t)(wid >> 3) * (2*MBYTES);
    gemm128(sb, aOff, aOff + MBYTES, OFF_B2H, OFF_B2L, acc, wid & 7, lane);
    // ---- epilogue: gelu + split -> gmem blobs ----
    int t = blk*2 + (wid >> 3);
    uint32_t* oH = (uint32_t*)(g_kbspH + (size_t)t*16384);
    uint32_t* oL = (uint32_t*)(g_kbspL + (size_t)t*16384);
    int row_lo = (wid & 7)*16 + (lane >> 2);
    #pragma unroll
    for (int nt = 0; nt < 16; nt++) {
        int col = nt*8 + (lane & 3)*2;
        float b20 = sb2[col], b21 = sb2[col+1];
        int cp = col >> 1;
        float f0 = gelu(acc[nt*4+0] + b20), f1 = gelu(acc[nt*4+1] + b21);
        uint32_t hi = pack2(f0, f1);
        oH[row_lo*64 + cp] = hi; oL[row_lo*64 + cp] = pack2lo(f0, f1, hi);
        float f2 = gelu(acc[nt*4+2] + b20), f3 = gelu(acc[nt*4+3] + b21);
        uint32_t hi2 = pack2(f2, f3);
        oH[(row_lo+8)*64 + cp] = hi2; oL[(row_lo+8)*64 + cp] = pack2lo(f2, f3, hi2);
    }
}

__global__ void k_zero_agg() {
    size_t idx = (size_t)blockIdx.x*blockDim.x + threadIdx.x;
    if (idx < (size_t)NN*NG*HID) g_agg[idx] = 0.f;
}

// ---------------- K6: edge GEMM + scatter — 2 tiles, 512 threads ----------------
__global__ void __launch_bounds__(512) k_edge(const int* __restrict__ ei, int l) {
    int blk = blockIdx.x, tid = threadIdx.x;
    int wid = tid >> 5, lane = tid & 31;
    uint32_t sb = smem_u32(dsm);
    cp_blob_a<512>(sb,            g_kbspH + (size_t)(2*blk)*16384, tid);
    cp_blob_a<512>(sb + MBYTES,   g_kbspL + (size_t)(2*blk)*16384, tid);
    cp_blob_a<512>(sb + 2*MBYTES, g_kbspH + (size_t)(2*blk+1)*16384, tid);
    cp_blob_a<512>(sb + 3*MBYTES, g_kbspL + (size_t)(2*blk+1)*16384, tid);
    cp_blob_a<512>(sb + OFF_B2H,  g_BWkH + (size_t)l*16384, tid);
    cp_blob_a<512>(sb + OFF_B2L,  g_BWkL + (size_t)l*16384, tid);
    CPA_COMMIT();
    CPA_WAIT0();
    __syncthreads();
    float acc[64];
    #pragma unroll
    for (int i = 0; i < 64; i++) acc[i] = 0.f;
    uint32_t aOff = (uint32_t)(wid >> 3) * (2*MBYTES);
    gemm128(sb, aOff, aOff + MBYTES, OFF_B2H, OFF_B2L, acc, wid & 7, lane);
    __syncthreads();                        // B region dead -> staging
    float* stage = (float*)(dsm + OFF_B2H);
    int row_lo = (wid & 7)*16 + (lane >> 2);
    for (int tp = 0; tp < 2; tp++) {
        if ((wid >> 3) == tp) {
            #pragma unroll
            for (int nt = 0; nt < 16; nt++) {
                int col = nt*8 + (lane & 3)*2;
                stage[row_lo*TSTRIDE + col]       = acc[nt*4+0];
                stage[row_lo*TSTRIDE + col+1]     = acc[nt*4+1];
                stage[(row_lo+8)*TSTRIDE + col]   = acc[nt*4+2];
                stage[(row_lo+8)*TSTRIDE + col+1] = acc[nt*4+3];
            }
        }
        __syncthreads();
        int c = tid & 127, rb = tid >> 7;
        int base = blk*256 + tp*128;
        for (int rr = rb; rr < 128; rr += 4) {
            int gr = base + rr, e = gr/12, p = gr - e*12;
            int sn = ei[e], rn = ei[NE + e];
            float m = stage[rr*TSTRIDE + c] * g_h[((size_t)sn*12 + p)*HID + c];
            atomicAdd(&g_agg[((size_t)rn*12 + p)*HID + c], m);
        }
        __syncthreads();
    }
}

// ---------------- K7a: conv + LN -> hn blobs ----------------
__global__ void k_node_pre(const float* __restrict__ bconv, const float* __restrict__ lng,
                           const float* __restrict__ lnb, int l) {
    int i = blockIdx.x, c = threadIdx.x;
    __shared__ float sA[NG][HID], sH[NG][HID], mu[NG], rstd[NG];
    {
        const float4* src = (const float4*)(g_agg + (size_t)i*NG*HID);
        float4* dst = (float4*)&sA[0][0];
        for (int k = c; k < NG*HID/4; k += HID) dst[k] = src[k];
    }
    __syncthreads();
    const float* fkl = g_fk + (size_t)l*NG*NG*HID;
    float bcv = bconv[l*HID + c];
    #pragma unroll
    for (int p = 0; p < NG; p++) {
        float s = 0.f;
        #pragma unroll
        for (int o = 0; o < NG; o++) s += sA[o][c]*fkl[(p*NG + o)*HID + c];
        sH[p][c] = s*(1.0f/NG) + bcv;
    }
    __syncthreads();
    if (c < NG) {
        float s = 0.f, s2 = 0.f;
        for (int k = 0; k < HID; k++) { float v = sH[c][k]; s += v; s2 += v*v; }
        float m = s/HID; mu[c] = m; rstd[c] = rsqrtf(s2/HID - m*m + 1e-5f);
    }
    __syncthreads();
    float g = lng[l*HID+c], bbv = lnb[l*HID+c];
    float hn[NG];
    #pragma unroll
    for (int p = 0; p < NG; p++) hn[p] = (sH[p][c]-mu[p])*rstd[p]*g + bbv;
    __syncthreads();
    #pragma unroll
    for (int p = 0; p < NG; p++) sH[p][c] = hn[p];
    __syncthreads();
    for (int i2 = c; i2 < NG*64; i2 += HID) {
        int p = i2 >> 6, c2 = i2 & 63;
        int gr = i*12 + p, tt = gr >> 7, rr = gr & 127;
        float f0 = sH[p][2*c2], f1 = sH[p][2*c2+1];
        uint32_t hi = pack2(f0, f1), lo = pack2lo(f0, f1, hi);
        ((uint32_t*)(g_hnH + (size_t)tt*16384))[rr*64 + c2] = hi;
        ((uint32_t*)(g_hnL + (size_t)tt*16384))[rr*64 + c2] = lo;
    }
}

// ---------------- K7b: MLP + residual + readout — 512 threads, N-split ----------------
__global__ void __launch_bounds__(512) k_mlp(
        const float* __restrict__ b1, const float* __restrict__ b2,
        const float* __restrict__ Wro, const float* __restrict__ bro, int l) {
    __shared__ float sWro[HID*9];
    int t = blockIdx.x, tid = threadIdx.x;
    int wid = tid >> 5, lane = tid & 31;
    int rowgrp = wid & 7, colgrp = wid >> 3;
    uint32_t sb = smem_u32(dsm);
    cp_blob_a<512>(sb + OFF_AH, g_hnH + (size_t)t*16384, tid);
    cp_blob_a<512>(sb + OFF_AL, g_hnL + (size_t)t*16384, tid);
    cp_blob_a<512>(sb + OFF_BH, g_BW1H + (size_t)(l*4)*16384, tid);
    cp_blob_a<512>(sb + OFF_BL, g_BW1L + (size_t)(l*4)*16384, tid);
    CPA_COMMIT();
    for (int i = tid; i < HID*9; i += 512) sWro[i] = Wro[(size_t)l*HID*9 + i];
    int row_lo = rowgrp*16 + (lane >> 2);
    float acc2[32];
    #pragma unroll
    for (int i = 0; i < 32; i++) acc2[i] = 0.f;
    for (int j = 0; j < 4; j++) {
        CPA_WAIT0();
        __syncthreads();                          // A + W1_j ready
        float acc1[32];
        #pragma unroll
        for (int i = 0; i < 32; i++) acc1[i] = 0.f;
        gemm128h(sb, OFF_AH, OFF_AL, OFF_BH, OFF_BL, acc1, rowgrp, colgrp, lane);
        __syncthreads();                          // all warps done reading W1_j
        cp_blob_a<512>(sb + OFF_BH, g_BW2H + (size_t)(l*4+j)*16384, tid);
        cp_blob_a<512>(sb + OFF_BL, g_BW2L + (size_t)(l*4+j)*16384, tid);
        CPA_COMMIT();
        // U epilogue overlaps W2 copy
        #pragma unroll
        for (int nt = 0; nt < 8; nt++) {
            int col = colgrp*64 + nt*8 + (lane & 3)*2;
            float bj0 = b1[(size_t)l*WHID + j*128 + col];
            float bj1 = b1[(size_t)l*WHID + j*128 + col+1];
            float f0 = gelu(acc1[nt*4+0] + bj0), f1 = gelu(acc1[nt*4+1] + bj1);
            uint32_t hi = pack2(f0, f1);
            uint32_t bo = row_lo*(MSTRIDE*2) + col*2;
            *(uint32_t*)(dsm + OFF_UH + bo) = hi;
            *(uint32_t*)(dsm + OFF_UL + bo) = pack2lo(f0, f1, hi);
            float f2 = gelu(acc1[nt*4+2] + bj0), f3 = gelu(acc1[nt*4+3] + bj1);
            uint32_t hi2 = pack2(f2, f3);
            uint32_t bo2 = (row_lo+8)*(MSTRIDE*2) + col*2;
            *(uint32_t*)(dsm + OFF_UH + bo2) = hi2;
            *(uint32_t*)(dsm + OFF_UL + bo2) = pack2lo(f2, f3, hi2);
        }
        CPA_WAIT0();
        __syncthreads();                          // W2_j + U ready
        gemm128h(sb, OFF_UH, OFF_UL, OFF_BH, OFF_BL, acc2, rowgrp, colgrp, lane);
        __syncthreads();                          // done reading W2_j
        if (j < 3) {
            cp_blob_a<512>(sb + OFF_BH, g_BW1H + (size_t)(l*4+j+1)*16384, tid);
            cp_blob_a<512>(sb + OFF_BL, g_BW1L + (size_t)(l*4+j+1)*16384, tid);
            CPA_COMMIT();
        }
    }
    // ---- final: residual + store h + readout ----
    float* tile = (float*)(dsm + OFF_BH);
    #pragma unroll
    for (int nt = 0; nt < 8; nt++) {
        int col = colgrp*64 + nt*8 + (lane & 3)*2;
        tile[row_lo*TSTRIDE + col]       = acc2[nt*4+0];
        tile[row_lo*TSTRIDE + col+1]     = acc2[nt*4+1];
        tile[(row_lo+8)*TSTRIDE + col]   = acc2[nt*4+2];
        tile[(row_lo+8)*TSTRIDE + col+1] = acc2[nt*4+3];
    }
    __syncthreads();
    {
        int r = tid >> 2, q = tid & 3;
        size_t gr = (size_t)t*128 + r;
        float ro[9];
        #pragma unroll
        for (int m = 0; m < 9; m++) ro[m] = 0.f;
        for (int k = q*32; k < q*32 + 32; k++) {
            float hnew = tile[r*TSTRIDE + k] + __ldg(&b2[(size_t)l*HID + k]) + g_h[gr*HID + k];
            g_h[gr*HID + k] = hnew;
            #pragma unroll
            for (int m = 0; m < 9; m++) ro[m] += hnew * sWro[k*9 + m];
        }
        #pragma unroll
        for (int m = 0; m < 9; m++) {
            ro[m] += __shfl_xor_sync(0xffffffffu, ro[m], 1);
            ro[m] += __shfl_xor_sync(0xffffffffu, ro[m], 2);
        }
        if (q == 0) {
            #pragma unroll
            for (int m = 0; m < 9; m++)
                g_readout[gr*9 + m] += (ro[m] + bro[l*9 + m]) * (1.0f/LAY);
        }
    }
}

// ---------------- final ----------------
__global__ void k_zero_out(float* out, int n) { int t = threadIdx.x; if (t < n) out[t] = 0.f; }

__global__ void k_final(const int* __restrict__ batch, float* __restrict__ out) {
    int i = blockIdx.x, t = threadIdx.x, b = batch[i];
    if (t < OUT_S) {
        float s = 0.f;
        #pragma unroll
        for (int n = 0; n < NG; n++) s += g_readout[(size_t)i*108 + n*9 + t];
        atomicAdd(&out[b*OUT_S + t], s*(1.0f/NG));
    } else if (t < OUT_S + 3) {
        int d = t - OUT_S;
        float s = 0.f;
        #pragma unroll
        for (int n = 0; n < NG; n++)
            s += g_readout[(size_t)i*108 + n*9 + 8]*g_nodegrid[i*36 + n*3 + d];
        atomicAdd(&out[BATCH*OUT_S + b*3 + d], s*(1.0f/NG));
    }
}

// ---------------- launch ----------------
extern "C" void kernel_launch(void* const* d_in, const int* in_sizes, int n_in,
                              void* d_out, int out_size) {
    const float* x     = (const float*)d_in[0];
    const float* vec   = (const float*)d_in[1];
    const float* pos   = (const float*)d_in[2];
    const float* Q     = (const float*)d_in[3];
    const float* Wsp1  = (const float*)d_in[4];
    const float* bsp1  = (const float*)d_in[5];
    const float* Wsp2  = (const float*)d_in[6];
    const float* bsp2  = (const float*)d_in[7];
    const float* Wsh1  = (const float*)d_in[8];
    const float* bsh1  = (const float*)d_in[9];
    const float* Wsh2  = (const float*)d_in[10];
    const float* bsh2  = (const float*)d_in[11];
    const float* Wemb  = (const float*)d_in[12];
    const float* Wk    = (const float*)d_in[13];
    const float* Wfk   = (const float*)d_in[14];
    const float* bconv = (const float*)d_in[15];
    const float* lng   = (const float*)d_in[16];
    const float* lnb   = (const float*)d_in[17];
    const float* W1    = (const float*)d_in[18];
    const float* b1    = (const float*)d_in[19];
    const float* W2    = (const float*)d_in[20];
    const float* b2    = (const float*)d_in[21];
    const float* Wro   = (const float*)d_in[22];
    const float* bro   = (const float*)d_in[23];
    const int*   ei    = (const int*)d_in[24];
    const int*   batch = (const int*)d_in[25];
    float* out = (float*)d_out;

    static int attr_done = 0;
    if (!attr_done) {
        cudaFuncSetAttribute(k_kbsp, cudaFuncAttributeMaxDynamicSharedMemorySize, SM_BIG);
        cudaFuncSetAttribute(k_edge, cudaFuncAttributeMaxDynamicSharedMemorySize, SM_BIG);
        cudaFuncSetAttribute(k_mlp,  cudaFuncAttributeMaxDynamicSharedMemorySize, SM_BIG);
        attr_done = 1;
    }

    // ncu captures launch #4 -> make it k_kbsp
    k_init_grid0<<<1, 32>>>();                                    // 1
    k_nodeinit<<<NN, HID>>>(x, vec, Q, batch, Wemb);              // 2
    k_pack_all<<<(458752 + 255)/256, 256>>>(Wsp2, Wk, W1, W2);    // 3
    k_kbsp<<<ETILES/2, 512, SM_BIG>>>(pos, ei, Wsp1, bsp1, bsp2); // 4 <- profiled
    k_kbsh<<<NG*NG, HID>>>(Wsh1, bsh1, Wsh2, bsh2);               // 5
    k_fk<<<LAY*NG*NG, HID>>>(Wfk);                                // 6

    for (int l = 0; l < LAY; l++) {
        k_zero_agg<<<(NN*NG*HID + 255)/256, 256>>>();
        k_edge<<<ETILES/2, 512, SM_BIG>>>(ei, l);
        k_node_pre<<<NN, HID>>>(bconv, lng, lnb, l);
        k_mlp<<<NTILES, 512, SM_BIG>>>(b1, b2, Wro, bro, l);
    }
    k_zero_out<<<1, 1024>>>(out, out_size);
    k_final<<<NN, 32>>>(batch, out);
}

// round 14
// speedup vs baseline: 1.6757x; 1.0437x over previous
#include <cuda_runtime.h>
#include <cuda_bf16.h>
#include <math.h>
#include <stdint.h>

#define NN     8000
#define NE     64000
#define BATCH  64
#define NG     12
#define HID    128
#define LAY    3
#define IN_S   16
#define OUT_S  8
#define WHID   512
#define ETILES 6000   // 768000/128
#define NTILES 750    // 96000/128

// f32 smem matrix: 128 rows x 132 floats (528B stride; 132%32=4 -> conflict-free ldmatrix)
#define FSTR   132
#define FMB    (128*FSTR*4)     // 67584 bytes per matrix
#define SM3    (3*FMB)          // 202752 dynamic smem
// kbsp/edge: A0@0, A1@FMB, B@2FMB ; mlp: A@0, B@FMB, U@2FMB

// ---------------- helpers ----------------
__device__ __forceinline__ uint32_t smem_u32(const void* p) {
    uint32_t a;
    asm("{ .reg .u64 t; cvta.to.shared.u64 t, %1; cvt.u32.u64 %0, t; }" : "=r"(a) : "l"(p));
    return a;
}
__device__ __forceinline__ void ldsm4(uint32_t addr, uint32_t* r) {
    asm volatile("ldmatrix.sync.aligned.m8n8.x4.shared.b16 {%0,%1,%2,%3}, [%4];"
        : "=r"(r[0]), "=r"(r[1]), "=r"(r[2]), "=r"(r[3]) : "r"(addr));
}
__device__ __forceinline__ void mma_tf32(float* d, const uint32_t* a, uint32_t b0, uint32_t b1) {
    asm volatile("mma.sync.aligned.m16n8k8.row.col.f32.tf32.tf32.f32 "
        "{%0,%1,%2,%3}, {%4,%5,%6,%7}, {%8,%9}, {%0,%1,%2,%3};"
        : "+f"(d[0]), "+f"(d[1]), "+f"(d[2]), "+f"(d[3])
        : "r"(a[0]), "r"(a[1]), "r"(a[2]), "r"(a[3]), "r"(b0), "r"(b1));
}
__device__ __forceinline__ float tf32r(float x) {
    uint32_t y;
    asm("cvt.rna.tf32.f32 %0, %1;" : "=r"(y) : "f"(x));
    return __uint_as_float(y);
}
__device__ __forceinline__ float gelu(float x) {
    return x * 0.5f * (1.0f + erff(x * 0.70710678118654752f));
}

// cp.async 16B copies of a 128x128 f32 gmem blob -> padded smem matrix
template<int NT>
__device__ __forceinline__ void cp_blob_f(uint32_t dst, const float* src, int tid) {
    for (int i = tid; i < 4096; i += NT) {
        int row = i >> 5, j = i & 31;
        asm volatile("cp.async.cg.shared.global [%0], [%1], 16;"
            :: "r"(dst + (uint32_t)(row*33 + j)*16), "l"((const char*)src + (size_t)i*16));
    }
}
#define CPA_COMMIT() asm volatile("cp.async.commit_group;" ::: "memory")
#define CPA_WAIT0()  asm volatile("cp.async.wait_group 0;" ::: "memory")

// full-N tf32 gemm: warp computes rows [wid*16,+16) x cols 0..127, acc[64]
__device__ __forceinline__ void gemm_full(uint32_t sb, uint32_t aOff, uint32_t bOff,
                                          float* acc, int wid, int lane) {
    uint32_t aRow  = wid*16 + (lane & 7) + ((lane >> 3) & 1) * 8;
    uint32_t aByte = (uint32_t)(lane >> 4) * 16;
    uint32_t bRowL = (lane & 7) + ((lane >> 4) << 3);
    uint32_t bByte = (uint32_t)((lane >> 3) & 1) * 16;
    #pragma unroll
    for (int k8 = 0; k8 < 16; k8++) {
        uint32_t ka = (uint32_t)k8 * 32;
        uint32_t a[4];
        ldsm4(sb + aOff + aRow*528 + ka + aByte, a);
        #pragma unroll
        for (int g = 0; g < 8; g++) {
            uint32_t b[4];
            ldsm4(sb + bOff + (g*16 + bRowL)*528 + ka + bByte, b);
            mma_tf32(acc + g*8,     a, b[0], b[1]);
            mma_tf32(acc + g*8 + 4, a, b[2], b[3]);
        }
    }
}
// half-N: rows [rowgrp*16,+16) x cols [colgrp*64,+64), acc[32]
__device__ __forceinline__ void gemm_half(uint32_t sb, uint32_t aOff, uint32_t bOff,
                                          float* acc, int rowgrp, int colgrp, int lane) {
    uint32_t aRow  = rowgrp*16 + (lane & 7) + ((lane >> 3) & 1) * 8;
    uint32_t aByte = (uint32_t)(lane >> 4) * 16;
    uint32_t bRowL = (lane & 7) + ((lane >> 4) << 3);
    uint32_t bByte = (uint32_t)((lane >> 3) & 1) * 16;
    #pragma unroll
    for (int k8 = 0; k8 < 16; k8++) {
        uint32_t ka = (uint32_t)k8 * 32;
        uint32_t a[4];
        ldsm4(sb + aOff + aRow*528 + ka + aByte, a);
        #pragma unroll
        for (int g = 0; g < 4; g++) {
            uint32_t b[4];
            ldsm4(sb + bOff + ((colgrp*64 + g*16) + bRowL)*528 + ka + bByte, b);
            mma_tf32(acc + g*8,     a, b[0], b[1]);
            mma_tf32(acc + g*8 + 4, a, b[2], b[3]);
        }
    }
}

// ---------------- device scratch ----------------
__device__ float g_grid0[NG*3];
__device__ float g_kbsh[NG*NG*HID];
__device__ float g_fk[LAY*NG*NG*HID];
__device__ float g_nodegrid[NN*NG*3];
__device__ float g_h[NN*NG*HID];
__device__ float g_agg[NN*NG*HID];
__device__ float g_readout[NN*NG*9];
__device__ float g_kbsp[(size_t)ETILES*16384];   // tf32-rounded f32 tiles, 393MB
__device__ float g_hn[(size_t)NTILES*16384];
__device__ float g_Bsp2[16384];                  // Bt[n][k] tf32-rounded
__device__ float g_BWk[3*16384];
__device__ float g_BW1[12*16384];
__device__ float g_BW2[12*16384];

extern __shared__ __align__(16) char dsm[];

// ---------------- setup ----------------
__global__ void k_init_grid0() {
    int i = threadIdx.x;
    if (i < NG) {
        float fi = (float)i;
        float theta = (6.2831853071795865f * fi) / 1.6180339887498949f;
        float z = 1.0f - (2.0f*fi + 1.0f) / (float)NG;
        float r = sqrtf(fmaxf(1.0f - z*z, 0.0f));
        g_grid0[i*3+0] = r*cosf(theta); g_grid0[i*3+1] = r*sinf(theta); g_grid0[i*3+2] = z;
    }
}

__global__ void k_pack_all(const float* __restrict__ Wsp2, const float* __restrict__ Wk,
                           const float* __restrict__ W1, const float* __restrict__ W2) {
    int idx = blockIdx.x * blockDim.x + threadIdx.x;
    const float* src; float* dst;
    int K, N, off, blobbase;
    if (idx < 16384) {
        src = Wsp2; dst = g_Bsp2; K = 128; N = 128; off = idx; blobbase = 0;
    } else if (idx < 65536) {
        int r = idx - 16384; int l = r >> 14; off = r & 16383;
        src = Wk + (size_t)l*16384; dst = g_BWk; K = 128; N = 128; blobbase = l;
    } else if (idx < 262144) {
        int r = idx - 65536; int l = r >> 16; off = r & 65535;
        src = W1 + (size_t)l*65536; dst = g_BW1; K = 128; N = 512; blobbase = l*4;
    } else if (idx < 458752) {
        int r = idx - 262144; int l = r >> 16; off = r & 65535;
        src = W2 + (size_t)l*65536; dst = g_BW2; K = 512; N = 128; blobbase = l*4;
    } else return;
    int k = off / N, n = off % N;
    int blob = blobbase + (n >> 7) * (K >> 7) + (k >> 7);
    int o = (n & 127)*128 + (k & 127);
    dst[(size_t)blob*16384 + o] = tf32r(src[off]);
}

__global__ void k_kbsh(const float* __restrict__ Wsh1, const float* __restrict__ bsh1,
                       const float* __restrict__ Wsh2, const float* __restrict__ bsh2) {
    int row = blockIdx.x, p = row/NG, o = row%NG, c = threadIdx.x;
    __shared__ float h1[HID];
    float t = g_grid0[p*3]*g_grid0[o*3] + g_grid0[p*3+1]*g_grid0[o*3+1] + g_grid0[p*3+2]*g_grid0[o*3+2];
    h1[c] = gelu(bsh1[c] + t*Wsh1[c] + t*t*Wsh1[HID+c] + t*t*t*Wsh1[2*HID+c]);
    __syncthreads();
    float acc = bsh2[c];
    #pragma unroll 8
    for (int k = 0; k < HID; k++) acc += h1[k]*Wsh2[k*HID+c];
    g_kbsh[row*HID + c] = gelu(acc);
}

__global__ void k_fk(const float* __restrict__ Wfk) {
    int blk = blockIdx.x, l = blk/(NG*NG), row = blk%(NG*NG), c = threadIdx.x;
    __shared__ float kb[HID];
    kb[c] = g_kbsh[row*HID + c];
    __syncthreads();
    const float* W = Wfk + (size_t)l*HID*HID;
    float acc = 0.f;
    #pragma unroll 8
    for (int b = 0; b < HID; b++) acc += kb[b]*W[b*HID+c];
    g_fk[((size_t)l*NG*NG + row)*HID + c] = acc;
}

__global__ void k_nodeinit(const float* __restrict__ x, const float* __restrict__ vec,
                           const float* __restrict__ Q, const int* __restrict__ batch,
                           const float* __restrict__ Wemb) {
    int i = blockIdx.x, t = threadIdx.x;
    __shared__ float ng[NG][3], xv[NG][2], xs[IN_S];
    int b = batch[i];
    if (t < 36) {
        int n = t/3, d = t%3; float s = 0.f;
        #pragma unroll
        for (int j = 0; j < 3; j++) s += Q[b*9 + d*3 + j]*g_grid0[n*3+j];
        ng[n][d] = s; g_nodegrid[i*36 + t] = s;
    }
    if (t >= 64 && t < 64+IN_S) xs[t-64] = x[i*IN_S + (t-64)];
    if (t < 108) g_readout[(size_t)i*108 + t] = 0.f;
    __syncthreads();
    if (t < 24) {
        int n = t/2, v = t%2;
        xv[n][v] = vec[i*6+v*3]*ng[n][0] + vec[i*6+v*3+1]*ng[n][1] + vec[i*6+v*3+2]*ng[n][2];
    }
    __syncthreads();
    int c = t; float hx = 0.f;
    #pragma unroll
    for (int s = 0; s < IN_S; s++) hx += xs[s]*Wemb[s*HID+c];
    float w16 = Wemb[16*HID+c], w17 = Wemb[17*HID+c];
    #pragma unroll
    for (int n = 0; n < NG; n++)
        g_h[(size_t)i*NG*HID + n*HID + c] = hx + xv[n][0]*w16 + xv[n][1]*w17;
}

// ---------------- K4: kbsp — 2 tiles per block, 512 threads, tf32 ----------------
__global__ void __launch_bounds__(512) k_kbsp(
        const float* __restrict__ pos, const int* __restrict__ ei,
        const float* __restrict__ Wsp1, const float* __restrict__ bsp1,
        const float* __restrict__ bsp2) {
    __shared__ float sW1[14*HID], sb1[HID], sb2[HID];
    int blk = blockIdx.x, tid = threadIdx.x;
    int wid = tid >> 5, lane = tid & 31;
    uint32_t sb = smem_u32(dsm);
    cp_blob_f<512>(sb + 2*FMB, g_Bsp2, tid);       // B overlaps the front
    CPA_COMMIT();
    for (int i = tid; i < 14*HID; i += 512) sW1[i] = Wsp1[i];
    if (tid < HID) { sb1[tid] = bsp1[tid]; sb2[tid] = bsp2[tid]; }
    // ---- front: h1 rows 0..255 -> A0/A1 (f32 tf32-rounded) ----
    int r = tid >> 1, half = tid & 1;
    int gr = blk*256 + r, e = gr/12, p = gr - e*12;
    int sn = ei[e], rn = ei[NE + e];
    float rx = pos[sn*3]-pos[rn*3], ry = pos[sn*3+1]-pos[rn*3+1], rz = pos[sn*3+2]-pos[rn*3+2];
    float gx = g_nodegrid[rn*36+p*3], gy = g_nodegrid[rn*36+p*3+1], gz = g_nodegrid[rn*36+p*3+2];
    float a = rx*gx + ry*gy + rz*gz;
    float vx = rx-a*gx, vy = ry-a*gy, vz = rz-a*gz;
    float bb = sqrtf(vx*vx + vy*vy + vz*vz);
    float pf[14] = {a, bb, a*a, a*bb, bb*a, bb*bb, a*a*a, a*a*bb, a*bb*a, a*bb*bb,
                    bb*a*a, bb*a*bb, bb*bb*a, bb*bb*bb};
    __syncthreads();
    {
        uint32_t aBase = (uint32_t)(r >> 7) * FMB;
        int rr = r & 127;
        for (int c2 = half*32; c2 < half*32 + 32; c2++) {
            float f0 = sb1[2*c2], f1 = sb1[2*c2+1];
            #pragma unroll
            for (int j = 0; j < 14; j++) {
                f0 += pf[j]*sW1[j*HID + 2*c2];
                f1 += pf[j]*sW1[j*HID + 2*c2+1];
            }
            float2 v; v.x = tf32r(gelu(f0)); v.y = tf32r(gelu(f1));
            *(float2*)(dsm + aBase + rr*528 + c2*8) = v;
        }
    }
    CPA_WAIT0();
    __syncthreads();
    float acc[64];
    #pragma unroll
    for (int i = 0; i < 64; i++) acc[i] = 0.f;
    uint32_t aOff = (uint32_t)(wid >> 3) * FMB;
    gemm_full(sb, aOff, 2*FMB, acc, wid & 7, lane);
    // ---- epilogue: gelu + tf32 round -> gmem blob ----
    int t = blk*2 + (wid >> 3);
    float* o = g_kbsp + (size_t)t*16384;
    int row_lo = (wid & 7)*16 + (lane >> 2);
    #pragma unroll
    for (int nt = 0; nt < 16; nt++) {
        int col = nt*8 + (lane & 3)*2;
        float b20 = sb2[col], b21 = sb2[col+1];
        float2 v0; v0.x = tf32r(gelu(acc[nt*4+0] + b20)); v0.y = tf32r(gelu(acc[nt*4+1] + b21));
        *(float2*)(o + row_lo*128 + col) = v0;
        float2 v1; v1.x = tf32r(gelu(acc[nt*4+2] + b20)); v1.y = tf32r(gelu(acc[nt*4+3] + b21));
        *(float2*)(o + (row_lo+8)*128 + col) = v1;
    }
}

__global__ void k_zero_agg() {
    size_t idx = (size_t)blockIdx.x*blockDim.x + threadIdx.x;
    if (idx < (size_t)NN*NG*HID) g_agg[idx] = 0.f;
}

// ---------------- K6: edge GEMM + scatter — 2 tiles, 512 threads ----------------
__global__ void __launch_bounds__(512) k_edge(const int* __restrict__ ei, int l) {
    int blk = blockIdx.x, tid = threadIdx.x;
    int wid = tid >> 5, lane = tid & 31;
    uint32_t sb = smem_u32(dsm);
    cp_blob_f<512>(sb,         g_kbsp + (size_t)(2*blk)*16384, tid);
    cp_blob_f<512>(sb + FMB,   g_kbsp + (size_t)(2*blk+1)*16384, tid);
    cp_blob_f<512>(sb + 2*FMB, g_BWk + (size_t)l*16384, tid);
    CPA_COMMIT();
    CPA_WAIT0();
    __syncthreads();
    float acc[64];
    #pragma unroll
    for (int i = 0; i < 64; i++) acc[i] = 0.f;
    uint32_t aOff = (uint32_t)(wid >> 3) * FMB;
    gemm_full(sb, aOff, 2*FMB, acc, wid & 7, lane);
    __syncthreads();                        // B region dead -> staging
    float* stage = (float*)(dsm + 2*FMB);
    int row_lo = (wid & 7)*16 + (lane >> 2);
    for (int tp = 0; tp < 2; tp++) {
        if ((wid >> 3) == tp) {
            #pragma unroll
            for (int nt = 0; nt < 16; nt++) {
                int col = nt*8 + (lane & 3)*2;
                stage[row_lo*FSTR + col]       = acc[nt*4+0];
                stage[row_lo*FSTR + col+1]     = acc[nt*4+1];
                stage[(row_lo+8)*FSTR + col]   = acc[nt*4+2];
                stage[(row_lo+8)*FSTR + col+1] = acc[nt*4+3];
            }
        }
        __syncthreads();
        int c = tid & 127, rb = tid >> 7;
        int base = blk*256 + tp*128;
        for (int rr = rb; rr < 128; rr += 4) {
            int gr = base + rr, e = gr/12, p = gr - e*12;
            int sn = ei[e], rn = ei[NE + e];
            float m = stage[rr*FSTR + c] * g_h[((size_t)sn*12 + p)*HID + c];
            atomicAdd(&g_agg[((size_t)rn*12 + p)*HID + c], m);
        }
        __syncthreads();
    }
}

// ---------------- K7a: conv + LN -> hn blobs ----------------
__global__ void k_node_pre(const float* __restrict__ bconv, const float* __restrict__ lng,
                           const float* __restrict__ lnb, int l) {
    int i = blockIdx.x, c = threadIdx.x;
    __shared__ float sA[NG][HID], sH[NG][HID], mu[NG], rstd[NG];
    {
        const float4* src = (const float4*)(g_agg + (size_t)i*NG*HID);
        float4* dst = (float4*)&sA[0][0];
        for (int k = c; k < NG*HID/4; k += HID) dst[k] = src[k];
    }
    __syncthreads();
    const float* fkl = g_fk + (size_t)l*NG*NG*HID;
    float bcv = bconv[l*HID + c];
    #pragma unroll
    for (int p = 0; p < NG; p++) {
        float s = 0.f;
        #pragma unroll
        for (int o = 0; o < NG; o++) s += sA[o][c]*fkl[(p*NG + o)*HID + c];
        sH[p][c] = s*(1.0f/NG) + bcv;
    }
    __syncthreads();
    if (c < NG) {
        float s = 0.f, s2 = 0.f;
        for (int k = 0; k < HID; k++) { float v = sH[c][k]; s += v; s2 += v*v; }
        float m = s/HID; mu[c] = m; rstd[c] = rsqrtf(s2/HID - m*m + 1e-5f);
    }
    __syncthreads();
    float g = lng[l*HID+c], bbv = lnb[l*HID+c];
    float hn[NG];
    #pragma unroll
    for (int p = 0; p < NG; p++) hn[p] = (sH[p][c]-mu[p])*rstd[p]*g + bbv;
    __syncthreads();
    #pragma unroll
    for (int p = 0; p < NG; p++) sH[p][c] = hn[p];
    __syncthreads();
    for (int i2 = c; i2 < NG*64; i2 += HID) {
        int p = i2 >> 6, c2 = i2 & 63;
        int gr = i*12 + p, tt = gr >> 7, rr = gr & 127;
        float2 v; v.x = tf32r(sH[p][2*c2]); v.y = tf32r(sH[p][2*c2+1]);
        *(float2*)(g_hn + (size_t)tt*16384 + rr*128 + 2*c2) = v;
    }
}

// ---------------- K7b: MLP + residual + readout — 512 threads, N-split ----------------
__global__ void __launch_bounds__(512) k_mlp(
        const float* __restrict__ b1, const float* __restrict__ b2,
        const float* __restrict__ Wro, const float* __restrict__ bro, int l) {
    __shared__ float sWro[HID*9];
    int t = blockIdx.x, tid = threadIdx.x;
    int wid = tid >> 5, lane = tid & 31;
    int rowgrp = wid & 7, colgrp = wid >> 3;
    uint32_t sb = smem_u32(dsm);
    cp_blob_f<512>(sb,       g_hn + (size_t)t*16384, tid);
    cp_blob_f<512>(sb + FMB, g_BW1 + (size_t)(l*4)*16384, tid);
    CPA_COMMIT();
    for (int i = tid; i < HID*9; i += 512) sWro[i] = Wro[(size_t)l*HID*9 + i];
    int row_lo = rowgrp*16 + (lane >> 2);
    float acc2[32];
    #pragma unroll
    for (int i = 0; i < 32; i++) acc2[i] = 0.f;
    for (int j = 0; j < 4; j++) {
        CPA_WAIT0();
        __syncthreads();                          // A + W1_j ready
        float acc1[32];
        #pragma unroll
        for (int i = 0; i < 32; i++) acc1[i] = 0.f;
        gemm_half(sb, 0, FMB, acc1, rowgrp, colgrp, lane);
        __syncthreads();                          // done reading W1_j
        cp_blob_f<512>(sb + FMB, g_BW2 + (size_t)(l*4+j)*16384, tid);
        CPA_COMMIT();
        // U epilogue overlaps W2 copy
        #pragma unroll
        for (int nt = 0; nt < 8; nt++) {
            int col = colgrp*64 + nt*8 + (lane & 3)*2;
            float bj0 = b1[(size_t)l*WHID + j*128 + col];
            float bj1 = b1[(size_t)l*WHID + j*128 + col+1];
            float2 v0; v0.x = tf32r(gelu(acc1[nt*4+0] + bj0)); v0.y = tf32r(gelu(acc1[nt*4+1] + bj1));
            *(float2*)(dsm + 2*FMB + row_lo*528 + col*4) = v0;
            float2 v1; v1.x = tf32r(gelu(acc1[nt*4+2] + bj0)); v1.y = tf32r(gelu(acc1[nt*4+3] + bj1));
            *(float2*)(dsm + 2*FMB + (row_lo+8)*528 + col*4) = v1;
        }
        CPA_WAIT0();
        __syncthreads();                          // W2_j + U ready
        gemm_half(sb, 2*FMB, FMB, acc2, rowgrp, colgrp, lane);
        __syncthreads();                          // done reading W2_j
        if (j < 3) {
            cp_blob_f<512>(sb + FMB, g_BW1 + (size_t)(l*4+j+1)*16384, tid);
            CPA_COMMIT();
        }
    }
    // ---- final: residual + store h + readout ----
    float* tile = (float*)(dsm + FMB);
    #pragma unroll
    for (int nt = 0; nt < 8; nt++) {
        int col = colgrp*64 + nt*8 + (lane & 3)*2;
        tile[row_lo*FSTR + col]       = acc2[nt*4+0];
        tile[row_lo*FSTR + col+1]     = acc2[nt*4+1];
        tile[(row_lo+8)*FSTR + col]   = acc2[nt*4+2];
        tile[(row_lo+8)*FSTR + col+1] = acc2[nt*4+3];
    }
    __syncthreads();
    {
        int r = tid >> 2, q = tid & 3;
        size_t gr = (size_t)t*128 + r;
        float ro[9];
        #pragma unroll
        for (int m = 0; m < 9; m++) ro[m] = 0.f;
        for (int k = q*32; k < q*32 + 32; k++) {
            float hnew = tile[r*FSTR + k] + __ldg(&b2[(size_t)l*HID + k]) + g_h[gr*HID + k];
            g_h[gr*HID + k] = hnew;
            #pragma unroll
            for (int m = 0; m < 9; m++) ro[m] += hnew * sWro[k*9 + m];
        }
        #pragma unroll
        for (int m = 0; m < 9; m++) {
            ro[m] += __shfl_xor_sync(0xffffffffu, ro[m], 1);
            ro[m] += __shfl_xor_sync(0xffffffffu, ro[m], 2);
        }
        if (q == 0) {
            #pragma unroll
            for (int m = 0; m < 9; m++)
                g_readout[gr*9 + m] += (ro[m] + bro[l*9 + m]) * (1.0f/LAY);
        }
    }
}

// ---------------- final ----------------
__global__ void k_zero_out(float* out, int n) { int t = threadIdx.x; if (t < n) out[t] = 0.f; }

__global__ void k_final(const int* __restrict__ batch, float* __restrict__ out) {
    int i = blockIdx.x, t = threadIdx.x, b = batch[i];
    if (t < OUT_S) {
        float s = 0.f;
        #pragma unroll
        for (int n = 0; n < NG; n++) s += g_readout[(size_t)i*108 + n*9 + t];
        atomicAdd(&out[b*OUT_S + t], s*(1.0f/NG));
    } else if (t < OUT_S + 3) {
        int d = t - OUT_S;
        float s = 0.f;
        #pragma unroll
        for (int n = 0; n < NG; n++)
            s += g_readout[(size_t)i*108 + n*9 + 8]*g_nodegrid[i*36 + n*3 + d];
        atomicAdd(&out[BATCH*OUT_S + b*3 + d], s*(1.0f/NG));
    }
}

// ---------------- launch ----------------
extern "C" void kernel_launch(void* const* d_in, const int* in_sizes, int n_in,
                              void* d_out, int out_size) {
    const float* x     = (const float*)d_in[0];
    const float* vec   = (const float*)d_in[1];
    const float* pos   = (const float*)d_in[2];
    const float* Q     = (const float*)d_in[3];
    const float* Wsp1  = (const float*)d_in[4];
    const float* bsp1  = (const float*)d_in[5];
    const float* Wsp2  = (const float*)d_in[6];
    const float* bsp2  = (const float*)d_in[7];
    const float* Wsh1  = (const float*)d_in[8];
    const float* bsh1  = (const float*)d_in[9];
    const float* Wsh2  = (const float*)d_in[10];
    const float* bsh2  = (const float*)d_in[11];
    const float* Wemb  = (const float*)d_in[12];
    const float* Wk    = (const float*)d_in[13];
    const float* Wfk   = (const float*)d_in[14];
    const float* bconv = (const float*)d_in[15];
    const float* lng   = (const float*)d_in[16];
    const float* lnb   = (const float*)d_in[17];
    const float* W1    = (const float*)d_in[18];
    const float* b1    = (const float*)d_in[19];
    const float* W2    = (const float*)d_in[20];
    const float* b2    = (const float*)d_in[21];
    const float* Wro   = (const float*)d_in[22];
    const float* bro   = (const float*)d_in[23];
    const int*   ei    = (const int*)d_in[24];
    const int*   batch = (const int*)d_in[25];
    float* out = (float*)d_out;

    static int attr_done = 0;
    if (!attr_done) {
        cudaFuncSetAttribute(k_kbsp, cudaFuncAttributeMaxDynamicSharedMemorySize, SM3);
        cudaFuncSetAttribute(k_edge, cudaFuncAttributeMaxDynamicSharedMemorySize, SM3);
        cudaFuncSetAttribute(k_mlp,  cudaFuncAttributeMaxDynamicSharedMemorySize, SM3);
        attr_done = 1;
    }

    // ncu captures launch #4 -> keep it k_kbsp
    k_init_grid0<<<1, 32>>>();                                    // 1
    k_nodeinit<<<NN, HID>>>(x, vec, Q, batch, Wemb);              // 2
    k_pack_all<<<(458752 + 255)/256, 256>>>(Wsp2, Wk, W1, W2);    // 3
    k_kbsp<<<ETILES/2, 512, SM3>>>(pos, ei, Wsp1, bsp1, bsp2);    // 4 <- profiled
    k_kbsh<<<NG*NG, HID>>>(Wsh1, bsh1, Wsh2, bsh2);               // 5
    k_fk<<<LAY*NG*NG, HID>>>(Wfk);                                // 6

    for (int l = 0; l < LAY; l++) {
        k_zero_agg<<<(NN*NG*HID + 255)/256, 256>>>();
        k_edge<<<ETILES/2, 512, SM3>>>(ei, l);
        k_node_pre<<<NN, HID>>>(bconv, lng, lnb, l);
        k_mlp<<<NTILES, 512, SM3>>>(b1, b2, Wro, bro, l);
    }
    k_zero_out<<<1, 1024>>>(out, out_size);
    k_final<<<NN, 32>>>(batch, out);
}

// round 15
// speedup vs baseline: 1.7932x; 1.0702x over previous
#include <cuda_runtime.h>
#include <cuda_bf16.h>
#include <math.h>
#include <stdint.h>

#define NN     8000
#define NE     64000
#define BATCH  64
#define NG     12
#define HID    128
#define LAY    3
#define IN_S   16
#define OUT_S  8
#define WHID   512
#define ETILES 6000   // 768000/128
#define NTILES 750    // 96000/128

// f32 smem matrix: 128 rows x 132 floats (528B stride)
#define FSTR   132
#define FMB    (128*FSTR*4)     // 67584 bytes per matrix
#define SM3    (3*FMB)          // 202752 dynamic smem

// ---------------- helpers ----------------
__device__ __forceinline__ uint32_t smem_u32(const void* p) {
    uint32_t a;
    asm("{ .reg .u64 t; cvta.to.shared.u64 t, %1; cvt.u32.u64 %0, t; }" : "=r"(a) : "l"(p));
    return a;
}
__device__ __forceinline__ void ldsm4(uint32_t addr, uint32_t* r) {
    asm volatile("ldmatrix.sync.aligned.m8n8.x4.shared.b16 {%0,%1,%2,%3}, [%4];"
        : "=r"(r[0]), "=r"(r[1]), "=r"(r[2]), "=r"(r[3]) : "r"(addr));
}
__device__ __forceinline__ void mma_tf32(float* d, const uint32_t* a, uint32_t b0, uint32_t b1) {
    asm volatile("mma.sync.aligned.m16n8k8.row.col.f32.tf32.tf32.f32 "
        "{%0,%1,%2,%3}, {%4,%5,%6,%7}, {%8,%9}, {%0,%1,%2,%3};"
        : "+f"(d[0]), "+f"(d[1]), "+f"(d[2]), "+f"(d[3])
        : "r"(a[0]), "r"(a[1]), "r"(a[2]), "r"(a[3]), "r"(b0), "r"(b1));
}
__device__ __forceinline__ float tf32r(float x) {
    uint32_t y;
    asm("cvt.rna.tf32.f32 %0, %1;" : "=r"(y) : "f"(x));
    return __uint_as_float(y);
}
__device__ __forceinline__ float gelu(float x) {
    return x * 0.5f * (1.0f + erff(x * 0.70710678118654752f));
}

// cp.async 16B copies of a 128x128 f32 gmem blob -> padded smem matrix
template<int NT>
__device__ __forceinline__ void cp_blob_f(uint32_t dst, const float* src, int tid) {
    for (int i = tid; i < 4096; i += NT) {
        int row = i >> 5, j = i & 31;
        asm volatile("cp.async.cg.shared.global [%0], [%1], 16;"
            :: "r"(dst + (uint32_t)(row*33 + j)*16), "l"((const char*)src + (size_t)i*16));
    }
}
#define CPA_COMMIT() asm volatile("cp.async.commit_group;" ::: "memory")
#define CPA_WAIT0()  asm volatile("cp.async.wait_group 0;" ::: "memory")

// m32 x n64 warp-tile tf32 gemm. acc[64] = [mf(2)][g(4)][8]
__device__ __forceinline__ void gemm32x64(uint32_t sb, uint32_t aOff, uint32_t bOff,
                                          float* acc, int mrow, int cg, int lane) {
    uint32_t aRow0 = mrow + (lane & 7) + ((lane >> 3) & 1) * 8;
    uint32_t aByte = (uint32_t)(lane >> 4) * 16;
    uint32_t bRowL = (lane & 7) + ((lane >> 4) << 3);
    uint32_t bByte = (uint32_t)((lane >> 3) & 1) * 16;
    #pragma unroll
    for (int k8 = 0; k8 < 16; k8++) {
        uint32_t ka = (uint32_t)k8 * 32;
        uint32_t a0[4], a1[4];
        ldsm4(sb + aOff + aRow0*528 + ka + aByte, a0);
        ldsm4(sb + aOff + (aRow0 + 16)*528 + ka + aByte, a1);
        #pragma unroll
        for (int g = 0; g < 4; g++) {
            uint32_t b[4];
            ldsm4(sb + bOff + ((cg*64 + g*16) + bRowL)*528 + ka + bByte, b);
            mma_tf32(acc + g*8,          a0, b[0], b[1]);
            mma_tf32(acc + g*8 + 4,      a0, b[2], b[3]);
            mma_tf32(acc + 32 + g*8,     a1, b[0], b[1]);
            mma_tf32(acc + 32 + g*8 + 4, a1, b[2], b[3]);
        }
    }
}
// m32 x n32 warp-tile tf32 gemm. acc[32] = [mf(2)][g(2)][8]
__device__ __forceinline__ void gemm32x32(uint32_t sb, uint32_t aOff, uint32_t bOff,
                                          float* acc, int mg, int cg, int lane) {
    uint32_t aRow0 = mg*32 + (lane & 7) + ((lane >> 3) & 1) * 8;
    uint32_t aByte = (uint32_t)(lane >> 4) * 16;
    uint32_t bRowL = (lane & 7) + ((lane >> 4) << 3);
    uint32_t bByte = (uint32_t)((lane >> 3) & 1) * 16;
    #pragma unroll
    for (int k8 = 0; k8 < 16; k8++) {
        uint32_t ka = (uint32_t)k8 * 32;
        uint32_t a0[4], a1[4];
        ldsm4(sb + aOff + aRow0*528 + ka + aByte, a0);
        ldsm4(sb + aOff + (aRow0 + 16)*528 + ka + aByte, a1);
        #pragma unroll
        for (int g = 0; g < 2; g++) {
            uint32_t b[4];
            ldsm4(sb + bOff + ((cg*32 + g*16) + bRowL)*528 + ka + bByte, b);
            mma_tf32(acc + g*8,          a0, b[0], b[1]);
            mma_tf32(acc + g*8 + 4,      a0, b[2], b[3]);
            mma_tf32(acc + 16 + g*8,     a1, b[0], b[1]);
            mma_tf32(acc + 16 + g*8 + 4, a1, b[2], b[3]);
        }
    }
}

// ---------------- device scratch ----------------
__device__ float g_grid0[NG*3];
__device__ float g_kbsh[NG*NG*HID];
__device__ float g_fk[LAY*NG*NG*HID];
__device__ float g_nodegrid[NN*NG*3];
__device__ float g_h[NN*NG*HID];
__device__ float g_agg[NN*NG*HID];
__device__ float g_readout[NN*NG*9];
__device__ float g_kbsp[(size_t)ETILES*16384];
__device__ float g_hn[(size_t)NTILES*16384];
__device__ float g_Bsp2[16384];
__device__ float g_BWk[3*16384];
__device__ float g_BW1[12*16384];
__device__ float g_BW2[12*16384];

extern __shared__ __align__(16) char dsm[];

// ---------------- K1: nodeinit (grid0 inline, zero agg/readout, h0) ----------------
__global__ void k_nodeinit(const float* __restrict__ x, const float* __restrict__ vec,
                           const float* __restrict__ Q, const int* __restrict__ batch,
                           const float* __restrict__ Wemb) {
    int i = blockIdx.x, t = threadIdx.x;
    __shared__ float ng0[NG*3];
    __shared__ float ng[NG][3], xv[NG][2], xs[IN_S];
    int b = batch[i];
    if (t < NG) {
        float fi = (float)t;
        float theta = (6.2831853071795865f * fi) / 1.6180339887498949f;
        float z = 1.0f - (2.0f*fi + 1.0f) / (float)NG;
        float r = sqrtf(fmaxf(1.0f - z*z, 0.0f));
        float cx = r*cosf(theta), cy = r*sinf(theta);
        ng0[t*3+0] = cx; ng0[t*3+1] = cy; ng0[t*3+2] = z;
        if (i == 0) { g_grid0[t*3+0] = cx; g_grid0[t*3+1] = cy; g_grid0[t*3+2] = z; }
    }
    if (t >= 64 && t < 64+IN_S) xs[t-64] = x[i*IN_S + (t-64)];
    if (t < 108) g_readout[(size_t)i*108 + t] = 0.f;
    __syncthreads();
    if (t < 36) {
        int n = t/3, d = t%3; float s = 0.f;
        #pragma unroll
        for (int j = 0; j < 3; j++) s += Q[b*9 + d*3 + j]*ng0[n*3+j];
        ng[n][d] = s; g_nodegrid[i*36 + t] = s;
    }
    __syncthreads();
    if (t < 24) {
        int n = t/2, v = t%2;
        xv[n][v] = vec[i*6+v*3]*ng[n][0] + vec[i*6+v*3+1]*ng[n][1] + vec[i*6+v*3+2]*ng[n][2];
    }
    __syncthreads();
    int c = t; float hx = 0.f;
    #pragma unroll
    for (int s = 0; s < IN_S; s++) hx += xs[s]*Wemb[s*HID+c];
    float w16 = Wemb[16*HID+c], w17 = Wemb[17*HID+c];
    #pragma unroll
    for (int n = 0; n < NG; n++) {
        g_h[(size_t)i*NG*HID + n*HID + c] = hx + xv[n][0]*w16 + xv[n][1]*w17;
        g_agg[(size_t)i*NG*HID + n*HID + c] = 0.f;     // zero for layer 0
    }
}

__global__ void k_pack_all(const float* __restrict__ Wsp2, const float* __restrict__ Wk,
                           const float* __restrict__ W1, const float* __restrict__ W2) {
    int idx = blockIdx.x * blockDim.x + threadIdx.x;
    const float* src; float* dst;
    int K, N, off, blobbase;
    if (idx < 16384) {
        src = Wsp2; dst = g_Bsp2; K = 128; N = 128; off = idx; blobbase = 0;
    } else if (idx < 65536) {
        int r = idx - 16384; int l = r >> 14; off = r & 16383;
        src = Wk + (size_t)l*16384; dst = g_BWk; K = 128; N = 128; blobbase = l;
    } else if (idx < 262144) {
        int r = idx - 65536; int l = r >> 16; off = r & 65535;
        src = W1 + (size_t)l*65536; dst = g_BW1; K = 128; N = 512; blobbase = l*4;
    } else if (idx < 458752) {
        int r = idx - 262144; int l = r >> 16; off = r & 65535;
        src = W2 + (size_t)l*65536; dst = g_BW2; K = 512; N = 128; blobbase = l*4;
    } else return;
    int k = off / N, n = off % N;
    int blob = blobbase + (n >> 7) * (K >> 7) + (k >> 7);
    int o = (n & 127)*128 + (k & 127);
    dst[(size_t)blob*16384 + o] = tf32r(src[off]);
}

__global__ void k_kbsh(const float* __restrict__ Wsh1, const float* __restrict__ bsh1,
                       const float* __restrict__ Wsh2, const float* __restrict__ bsh2) {
    int row = blockIdx.x, p = row/NG, o = row%NG, c = threadIdx.x;
    __shared__ float h1[HID];
    float t = g_grid0[p*3]*g_grid0[o*3] + g_grid0[p*3+1]*g_grid0[o*3+1] + g_grid0[p*3+2]*g_grid0[o*3+2];
    h1[c] = gelu(bsh1[c] + t*Wsh1[c] + t*t*Wsh1[HID+c] + t*t*t*Wsh1[2*HID+c]);
    __syncthreads();
    float acc = bsh2[c];
    #pragma unroll 8
    for (int k = 0; k < HID; k++) acc += h1[k]*Wsh2[k*HID+c];
    g_kbsh[row*HID + c] = gelu(acc);
}

__global__ void k_fk(const float* __restrict__ Wfk) {
    int blk = blockIdx.x, l = blk/(NG*NG), row = blk%(NG*NG), c = threadIdx.x;
    __shared__ float kb[HID];
    kb[c] = g_kbsh[row*HID + c];
    __syncthreads();
    const float* W = Wfk + (size_t)l*HID*HID;
    float acc = 0.f;
    #pragma unroll 8
    for (int b = 0; b < HID; b++) acc += kb[b]*W[b*HID+c];
    g_fk[((size_t)l*NG*NG + row)*HID + c] = acc;
}

// ---------------- K4: kbsp — 2 tiles per block, 512 threads, m32n64 ----------------
__global__ void __launch_bounds__(512) k_kbsp(
        const float* __restrict__ pos, const int* __restrict__ ei,
        const float* __restrict__ Wsp1, const float* __restrict__ bsp1,
        const float* __restrict__ bsp2) {
    __shared__ float sW1[14*HID], sb1[HID], sb2[HID];
    int blk = blockIdx.x, tid = threadIdx.x;
    int wid = tid >> 5, lane = tid & 31;
    uint32_t sb = smem_u32(dsm);
    cp_blob_f<512>(sb + 2*FMB, g_Bsp2, tid);
    CPA_COMMIT();
    for (int i = tid; i < 14*HID; i += 512) sW1[i] = Wsp1[i];
    if (tid < HID) { sb1[tid] = bsp1[tid]; sb2[tid] = bsp2[tid]; }
    // front
    int r = tid >> 1, half = tid & 1;
    int gr = blk*256 + r, e = gr/12, p = gr - e*12;
    int sn = ei[e], rn = ei[NE + e];
    float rx = pos[sn*3]-pos[rn*3], ry = pos[sn*3+1]-pos[rn*3+1], rz = pos[sn*3+2]-pos[rn*3+2];
    float gx = g_nodegrid[rn*36+p*3], gy = g_nodegrid[rn*36+p*3+1], gz = g_nodegrid[rn*36+p*3+2];
    float a = rx*gx + ry*gy + rz*gz;
    float vx = rx-a*gx, vy = ry-a*gy, vz = rz-a*gz;
    float bb = sqrtf(vx*vx + vy*vy + vz*vz);
    float pf[14] = {a, bb, a*a, a*bb, bb*a, bb*bb, a*a*a, a*a*bb, a*bb*a, a*bb*bb,
                    bb*a*a, bb*a*bb, bb*bb*a, bb*bb*bb};
    __syncthreads();
    {
        uint32_t aBase = (uint32_t)(r >> 7) * FMB;
        int rr = r & 127;
        for (int c2 = half*32; c2 < half*32 + 32; c2++) {
            float f0 = sb1[2*c2], f1 = sb1[2*c2+1];
            #pragma unroll
            for (int j = 0; j < 14; j++) {
                f0 += pf[j]*sW1[j*HID + 2*c2];
                f1 += pf[j]*sW1[j*HID + 2*c2+1];
            }
            float2 v; v.x = tf32r(gelu(f0)); v.y = tf32r(gelu(f1));
            *(float2*)(dsm + aBase + rr*528 + c2*8) = v;
        }
    }
    CPA_WAIT0();
    __syncthreads();
    float acc[64];
    #pragma unroll
    for (int i = 0; i < 64; i++) acc[i] = 0.f;
    int mg = wid >> 1, cg = wid & 1;           // mg 0..7 (32-row groups over 2 tiles), cg 0..1
    uint32_t aOff = (uint32_t)(mg >> 2) * FMB;
    gemm32x64(sb, aOff, 2*FMB, acc, (mg & 3)*32, cg, lane);
    // epilogue
    int t = blk*2 + (mg >> 2);
    float* o = g_kbsp + (size_t)t*16384;
    int rbase = (mg & 3)*32;
    #pragma unroll
    for (int mf = 0; mf < 2; mf++) {
        int row_lo = rbase + mf*16 + (lane >> 2);
        #pragma unroll
        for (int g = 0; g < 4; g++) {
            int c0 = cg*64 + g*16 + (lane & 3)*2;
            int ab = mf*32 + g*8;
            float b0 = sb2[c0], b1v = sb2[c0+1], b8 = sb2[c0+8], b9 = sb2[c0+9];
            float2 v;
            v.x = tf32r(gelu(acc[ab+0] + b0)); v.y = tf32r(gelu(acc[ab+1] + b1v));
            *(float2*)(o + row_lo*128 + c0) = v;
            v.x = tf32r(gelu(acc[ab+2] + b0)); v.y = tf32r(gelu(acc[ab+3] + b1v));
            *(float2*)(o + (row_lo+8)*128 + c0) = v;
            v.x = tf32r(gelu(acc[ab+4] + b8)); v.y = tf32r(gelu(acc[ab+5] + b9));
            *(float2*)(o + row_lo*128 + c0 + 8) = v;
            v.x = tf32r(gelu(acc[ab+6] + b8)); v.y = tf32r(gelu(acc[ab+7] + b9));
            *(float2*)(o + (row_lo+8)*128 + c0 + 8) = v;
        }
    }
}

__global__ void k_zero_agg() {
    size_t idx = (size_t)blockIdx.x*blockDim.x + threadIdx.x;
    if (idx < (size_t)NN*NG*HID) g_agg[idx] = 0.f;
}

// ---------------- K6: edge GEMM + scatter — 2 tiles, 512 threads, m32n64 ----------------
__global__ void __launch_bounds__(512) k_edge(const int* __restrict__ ei, int l) {
    int blk = blockIdx.x, tid = threadIdx.x;
    int wid = tid >> 5, lane = tid & 31;
    uint32_t sb = smem_u32(dsm);
    cp_blob_f<512>(sb,         g_kbsp + (size_t)(2*blk)*16384, tid);
    cp_blob_f<512>(sb + FMB,   g_kbsp + (size_t)(2*blk+1)*16384, tid);
    cp_blob_f<512>(sb + 2*FMB, g_BWk + (size_t)l*16384, tid);
    CPA_COMMIT();
    CPA_WAIT0();
    __syncthreads();
    float acc[64];
    #pragma unroll
    for (int i = 0; i < 64; i++) acc[i] = 0.f;
    int mg = wid >> 1, cg = wid & 1;
    uint32_t aOff = (uint32_t)(mg >> 2) * FMB;
    gemm32x64(sb, aOff, 2*FMB, acc, (mg & 3)*32, cg, lane);
    __syncthreads();                        // B region dead -> staging
    float* stage = (float*)(dsm + 2*FMB);
    int rbase = (mg & 3)*32;
    for (int tp = 0; tp < 2; tp++) {
        if ((mg >> 2) == tp) {
            #pragma unroll
            for (int mf = 0; mf < 2; mf++) {
                int row_lo = rbase + mf*16 + (lane >> 2);
                #pragma unroll
                for (int g = 0; g < 4; g++) {
                    int c0 = cg*64 + g*16 + (lane & 3)*2;
                    int ab = mf*32 + g*8;
                    stage[row_lo*FSTR + c0]         = acc[ab+0];
                    stage[row_lo*FSTR + c0+1]       = acc[ab+1];
                    stage[(row_lo+8)*FSTR + c0]     = acc[ab+2];
                    stage[(row_lo+8)*FSTR + c0+1]   = acc[ab+3];
                    stage[row_lo*FSTR + c0+8]       = acc[ab+4];
                    stage[row_lo*FSTR + c0+9]       = acc[ab+5];
                    stage[(row_lo+8)*FSTR + c0+8]   = acc[ab+6];
                    stage[(row_lo+8)*FSTR + c0+9]   = acc[ab+7];
                }
            }
        }
        __syncthreads();
        int c = tid & 127, rb = tid >> 7;
        int base = blk*256 + tp*128;
        for (int rr = rb; rr < 128; rr += 4) {
            int gr = base + rr, e = gr/12, p = gr - e*12;
            int sn = ei[e], rn = ei[NE + e];
            float m = stage[rr*FSTR + c] * g_h[((size_t)sn*12 + p)*HID + c];
            atomicAdd(&g_agg[((size_t)rn*12 + p)*HID + c], m);
        }
        __syncthreads();
    }
}

// ---------------- K7a: conv + LN -> hn blobs ----------------
__global__ void k_node_pre(const float* __restrict__ bconv, const float* __restrict__ lng,
                           const float* __restrict__ lnb, int l) {
    int i = blockIdx.x, c = threadIdx.x;
    __shared__ float sA[NG][HID], sH[NG][HID], mu[NG], rstd[NG];
    {
        const float4* src = (const float4*)(g_agg + (size_t)i*NG*HID);
        float4* dst = (float4*)&sA[0][0];
        for (int k = c; k < NG*HID/4; k += HID) dst[k] = src[k];
    }
    __syncthreads();
    const float* fkl = g_fk + (size_t)l*NG*NG*HID;
    float bcv = bconv[l*HID + c];
    #pragma unroll
    for (int p = 0; p < NG; p++) {
        float s = 0.f;
        #pragma unroll
        for (int o = 0; o < NG; o++) s += sA[o][c]*fkl[(p*NG + o)*HID + c];
        sH[p][c] = s*(1.0f/NG) + bcv;
    }
    __syncthreads();
    if (c < NG) {
        float s = 0.f, s2 = 0.f;
        for (int k = 0; k < HID; k++) { float v = sH[c][k]; s += v; s2 += v*v; }
        float m = s/HID; mu[c] = m; rstd[c] = rsqrtf(s2/HID - m*m + 1e-5f);
    }
    __syncthreads();
    float g = lng[l*HID+c], bbv = lnb[l*HID+c];
    float hn[NG];
    #pragma unroll
    for (int p = 0; p < NG; p++) hn[p] = (sH[p][c]-mu[p])*rstd[p]*g + bbv;
    __syncthreads();
    #pragma unroll
    for (int p = 0; p < NG; p++) sH[p][c] = hn[p];
    __syncthreads();
    for (int i2 = c; i2 < NG*64; i2 += HID) {
        int p = i2 >> 6, c2 = i2 & 63;
        int gr = i*12 + p, tt = gr >> 7, rr = gr & 127;
        float2 v; v.x = tf32r(sH[p][2*c2]); v.y = tf32r(sH[p][2*c2+1]);
        *(float2*)(g_hn + (size_t)tt*16384 + rr*128 + 2*c2) = v;
    }
}

// ---------------- K7b: MLP + residual + readout — 512 threads, m32n32 ----------------
__global__ void __launch_bounds__(512) k_mlp(
        const float* __restrict__ b1, const float* __restrict__ b2,
        const float* __restrict__ Wro, const float* __restrict__ bro, int l) {
    __shared__ float sWro[HID*9];
    int t = blockIdx.x, tid = threadIdx.x;
    int wid = tid >> 5, lane = tid & 31;
    int mg = wid >> 2, cg = wid & 3;           // 4 m-groups x 4 n-groups (n32)
    uint32_t sb = smem_u32(dsm);
    cp_blob_f<512>(sb,       g_hn + (size_t)t*16384, tid);
    cp_blob_f<512>(sb + FMB, g_BW1 + (size_t)(l*4)*16384, tid);
    CPA_COMMIT();
    for (int i = tid; i < HID*9; i += 512) sWro[i] = Wro[(size_t)l*HID*9 + i];
    float acc2[32];
    #pragma unroll
    for (int i = 0; i < 32; i++) acc2[i] = 0.f;
    for (int j = 0; j < 4; j++) {
        CPA_WAIT0();
        __syncthreads();                          // A + W1_j ready
        float acc1[32];
        #pragma unroll
        for (int i = 0; i < 32; i++) acc1[i] = 0.f;
        gemm32x32(sb, 0, FMB, acc1, mg, cg, lane);
        __syncthreads();                          // done reading W1_j
        cp_blob_f<512>(sb + FMB, g_BW2 + (size_t)(l*4+j)*16384, tid);
        CPA_COMMIT();
        // U epilogue overlaps W2 copy
        const float* bj = b1 + (size_t)l*WHID + j*128;
        #pragma unroll
        for (int mf = 0; mf < 2; mf++) {
            int row_lo = mg*32 + mf*16 + (lane >> 2);
            #pragma unroll
            for (int g = 0; g < 2; g++) {
                int c0 = cg*32 + g*16 + (lane & 3)*2;
                int ab = mf*16 + g*8;
                float bj0 = bj[c0], bj1 = bj[c0+1], bj8 = bj[c0+8], bj9 = bj[c0+9];
                float2 v;
                v.x = tf32r(gelu(acc1[ab+0] + bj0)); v.y = tf32r(gelu(acc1[ab+1] + bj1));
                *(float2*)(dsm + 2*FMB + row_lo*528 + c0*4) = v;
                v.x = tf32r(gelu(acc1[ab+2] + bj0)); v.y = tf32r(gelu(acc1[ab+3] + bj1));
                *(float2*)(dsm + 2*FMB + (row_lo+8)*528 + c0*4) = v;
                v.x = tf32r(gelu(acc1[ab+4] + bj8)); v.y = tf32r(gelu(acc1[ab+5] + bj9));
                *(float2*)(dsm + 2*FMB + row_lo*528 + (c0+8)*4) = v;
                v.x = tf32r(gelu(acc1[ab+6] + bj8)); v.y = tf32r(gelu(acc1[ab+7] + bj9));
                *(float2*)(dsm + 2*FMB + (row_lo+8)*528 + (c0+8)*4) = v;
            }
        }
        CPA_WAIT0();
        __syncthreads();                          // W2_j + U ready
        gemm32x32(sb, 2*FMB, FMB, acc2, mg, cg, lane);
        __syncthreads();                          // done reading W2_j
        if (j < 3) {
            cp_blob_f<512>(sb + FMB, g_BW1 + (size_t)(l*4+j+1)*16384, tid);
            CPA_COMMIT();
        }
    }
    // final: stage acc2, then residual + store h + readout
    float* tile = (float*)(dsm + FMB);
    #pragma unroll
    for (int mf = 0; mf < 2; mf++) {
        int row_lo = mg*32 + mf*16 + (lane >> 2);
        #pragma unroll
        for (int g = 0; g < 2; g++) {
            int c0 = cg*32 + g*16 + (lane & 3)*2;
            int ab = mf*16 + g*8;
            tile[row_lo*FSTR + c0]         = acc2[ab+0];
            tile[row_lo*FSTR + c0+1]       = acc2[ab+1];
            tile[(row_lo+8)*FSTR + c0]     = acc2[ab+2];
            tile[(row_lo+8)*FSTR + c0+1]   = acc2[ab+3];
            tile[row_lo*FSTR + c0+8]       = acc2[ab+4];
            tile[row_lo*FSTR + c0+9]       = acc2[ab+5];
            tile[(row_lo+8)*FSTR + c0+8]   = acc2[ab+6];
            tile[(row_lo+8)*FSTR + c0+9]   = acc2[ab+7];
        }
    }
    __syncthreads();
    {
        int r = tid >> 2, q = tid & 3;
        size_t gr = (size_t)t*128 + r;
        float ro[9];
        #pragma unroll
        for (int m = 0; m < 9; m++) ro[m] = 0.f;
        for (int k = q*32; k < q*32 + 32; k++) {
            float hnew = tile[r*FSTR + k] + __ldg(&b2[(size_t)l*HID + k]) + g_h[gr*HID + k];
            g_h[gr*HID + k] = hnew;
            #pragma unroll
            for (int m = 0; m < 9; m++) ro[m] += hnew * sWro[k*9 + m];
        }
        #pragma unroll
        for (int m = 0; m < 9; m++) {
            ro[m] += __shfl_xor_sync(0xffffffffu, ro[m], 1);
            ro[m] += __shfl_xor_sync(0xffffffffu, ro[m], 2);
        }
        if (q == 0) {
            #pragma unroll
            for (int m = 0; m < 9; m++)
                g_readout[gr*9 + m] += (ro[m] + bro[l*9 + m]) * (1.0f/LAY);
        }
    }
}

// ---------------- final ----------------
__global__ void k_zero_out(float* out, int n) { int t = threadIdx.x; if (t < n) out[t] = 0.f; }

__global__ void k_final(const int* __restrict__ batch, float* __restrict__ out) {
    int i = blockIdx.x, t = threadIdx.x, b = batch[i];
    if (t < OUT_S) {
        float s = 0.f;
        #pragma unroll
        for (int n = 0; n < NG; n++) s += g_readout[(size_t)i*108 + n*9 + t];
        atomicAdd(&out[b*OUT_S + t], s*(1.0f/NG));
    } else if (t < OUT_S + 3) {
        int d = t - OUT_S;
        float s = 0.f;
        #pragma unroll
        for (int n = 0; n < NG; n++)
            s += g_readout[(size_t)i*108 + n*9 + 8]*g_nodegrid[i*36 + n*3 + d];
        atomicAdd(&out[BATCH*OUT_S + b*3 + d], s*(1.0f/NG));
    }
}

// ---------------- launch ----------------
extern "C" void kernel_launch(void* const* d_in, const int* in_sizes, int n_in,
                              void* d_out, int out_size) {
    const float* x     = (const float*)d_in[0];
    const float* vec   = (const float*)d_in[1];
    const float* pos   = (const float*)d_in[2];
    const float* Q     = (const float*)d_in[3];
    const float* Wsp1  = (const float*)d_in[4];
    const float* bsp1  = (const float*)d_in[5];
    const float* Wsp2  = (const float*)d_in[6];
    const float* bsp2  = (const float*)d_in[7];
    const float* Wsh1  = (const float*)d_in[8];
    const float* bsh1  = (const float*)d_in[9];
    const float* Wsh2  = (const float*)d_in[10];
    const float* bsh2  = (const float*)d_in[11];
    const float* Wemb  = (const float*)d_in[12];
    const float* Wk    = (const float*)d_in[13];
    const float* Wfk   = (const float*)d_in[14];
    const float* bconv = (const float*)d_in[15];
    const float* lng   = (const float*)d_in[16];
    const float* lnb   = (const float*)d_in[17];
    const float* W1    = (const float*)d_in[18];
    const float* b1    = (const float*)d_in[19];
    const float* W2    = (const float*)d_in[20];
    const float* b2    = (const float*)d_in[21];
    const float* Wro   = (const float*)d_in[22];
    const float* bro   = (const float*)d_in[23];
    const int*   ei    = (const int*)d_in[24];
    const int*   batch = (const int*)d_in[25];
    float* out = (float*)d_out;

    static int attr_done = 0;
    if (!attr_done) {
        cudaFuncSetAttribute(k_kbsp, cudaFuncAttributeMaxDynamicSharedMemorySize, SM3);
        cudaFuncSetAttribute(k_edge, cudaFuncAttributeMaxDynamicSharedMemorySize, SM3);
        cudaFuncSetAttribute(k_mlp,  cudaFuncAttributeMaxDynamicSharedMemorySize, SM3);
        attr_done = 1;
    }

    // ncu captures launch #4 -> make it k_edge (never profiled yet)
    k_nodeinit<<<NN, HID>>>(x, vec, Q, batch, Wemb);              // 1 (also zeroes agg)
    k_pack_all<<<(458752 + 255)/256, 256>>>(Wsp2, Wk, W1, W2);    // 2
    k_kbsp<<<ETILES/2, 512, SM3>>>(pos, ei, Wsp1, bsp1, bsp2);    // 3
    k_edge<<<ETILES/2, 512, SM3>>>(ei, 0);                        // 4 <- profiled
    k_kbsh<<<NG*NG, HID>>>(Wsh1, bsh1, Wsh2, bsh2);               // 5
    k_fk<<<LAY*NG*NG, HID>>>(Wfk);                                // 6
    k_node_pre<<<NN, HID>>>(bconv, lng, lnb, 0);                  // 7
    k_mlp<<<NTILES, 512, SM3>>>(b1, b2, Wro, bro, 0);             // 8

    for (int l = 1; l < LAY; l++) {
        k_zero_agg<<<(NN*NG*HID + 255)/256, 256>>>();
        k_edge<<<ETILES/2, 512, SM3>>>(ei, l);
        k_node_pre<<<NN, HID>>>(bconv, lng, lnb, l);
        k_mlp<<<NTILES, 512, SM3>>>(b1, b2, Wro, bro, l);
    }
    k_zero_out<<<1, 1024>>>(out, out_size);
    k_final<<<NN, 32>>>(batch, out);
}